// round 13
// baseline (speedup 1.0000x reference)
#include <cuda_runtime.h>
#include <cuda_bf16.h>
#include <math.h>
#include <stdint.h>

#define B_   8
#define P_   128
#define N_   256
#define D_   128
#define M_   (B_*P_*N_)        // 262144 rows
#define ROWSTRIDE_ 32768       // N_*D_ elements between consecutive p for fixed (b,n)

// ---------------- scratch (device globals; no allocation allowed) ----------------
__device__ __align__(16) __nv_bfloat16 g_q_hi[(size_t)M_ * D_];
__device__ __align__(16) __nv_bfloat16 g_q_lo[(size_t)M_ * D_];
__device__ __align__(16) __nv_bfloat16 g_k_hi[(size_t)M_ * D_];
__device__ __align__(16) __nv_bfloat16 g_k_lo[(size_t)M_ * D_];
__device__ __align__(16) __nv_bfloat16 g_v_hi[(size_t)M_ * D_];
__device__ __align__(16) __nv_bfloat16 g_v_lo[(size_t)M_ * D_];
__device__ __align__(16) __nv_bfloat16 g_att_hi[(size_t)M_ * D_];
__device__ __align__(16) __nv_bfloat16 g_att_lo[(size_t)M_ * D_];
// weights transposed to [n][k], bf16-split. layout: Wq(32768) Wk Wv W1(16384) W2
__device__ __align__(16) __nv_bfloat16 g_wh[131072];
__device__ __align__(16) __nv_bfloat16 g_wl[131072];

// ---------------- helpers ----------------
__device__ __forceinline__ uint32_t smem_u32(const void* p) {
    uint32_t a;
    asm("{ .reg .u64 t; cvta.to.shared.u64 t, %1; cvt.u32.u64 %0, t; }" : "=r"(a) : "l"(p));
    return a;
}
__device__ __forceinline__ void split_bf16(float x, uint16_t& h, uint16_t& l) {
    __nv_bfloat16 hb = __float2bfloat16(x);
    __nv_bfloat16 lb = __float2bfloat16(x - __bfloat162float(hb));
    h = __bfloat16_as_ushort(hb);
    l = __bfloat16_as_ushort(lb);
}
__device__ __forceinline__ void split2(float a, float b, uint32_t& hi, uint32_t& lo) {
    uint16_t ha, la, hb, lb;
    split_bf16(a, ha, la);
    split_bf16(b, hb, lb);
    hi = (uint32_t)ha | ((uint32_t)hb << 16);
    lo = (uint32_t)la | ((uint32_t)lb << 16);
}
// exact bf16(hi)+bf16(lo) -> fp32 reconstruction
__device__ __forceinline__ float join_bf16(uint16_t h, uint16_t l) {
    return __uint_as_float((uint32_t)h << 16) + __uint_as_float((uint32_t)l << 16);
}
__device__ __forceinline__ void ldmatrix_x4(uint32_t* r, uint32_t addr) {
    asm volatile("ldmatrix.sync.aligned.m8n8.x4.shared.b16 {%0,%1,%2,%3}, [%4];"
                 : "=r"(r[0]), "=r"(r[1]), "=r"(r[2]), "=r"(r[3]) : "r"(addr));
}
__device__ __forceinline__ void mma_bf16(float* d, const uint32_t* a, const uint32_t* b) {
    asm volatile(
        "mma.sync.aligned.m16n8k16.row.col.f32.bf16.bf16.f32 "
        "{%0,%1,%2,%3}, {%4,%5,%6,%7}, {%8,%9}, {%0,%1,%2,%3};"
        : "+f"(d[0]), "+f"(d[1]), "+f"(d[2]), "+f"(d[3])
        : "r"(a[0]), "r"(a[1]), "r"(a[2]), "r"(a[3]), "r"(b[0]), "r"(b[1]));
}
__device__ __forceinline__ void cp_async16(uint32_t dst, const void* src) {
    asm volatile("cp.async.cg.shared.global [%0], [%1], 16;" :: "r"(dst), "l"(src));
}
__device__ __forceinline__ void cp_commit() {
    asm volatile("cp.async.commit_group;" ::: "memory");
}
__device__ __forceinline__ void cp_wait0() {
    asm volatile("cp.async.wait_group 0;" ::: "memory");
}

// ---------------- convert weights: W[k][n] fp32 -> transposed split bf16 ----------
__global__ void convert_w(const float* __restrict__ Wq, const float* __restrict__ Wk,
                          const float* __restrict__ Wv, const float* __restrict__ W1,
                          const float* __restrict__ W2)
{
    int id = blockIdx.x * 256 + threadIdx.x;      // < 131072
    const float* src; int K, n, k; size_t dofs;
    if (id < 98304) {
        int wi = id >> 15, rem = id & 32767;
        k = rem >> 7; n = rem & 127; K = 256;
        src = (wi == 0) ? Wq : (wi == 1) ? Wk : Wv;
        dofs = (size_t)wi * 32768;
    } else {
        int r2 = id - 98304;
        int wi = r2 >> 14, rem = r2 & 16383;
        k = rem >> 7; n = rem & 127; K = 128;
        src = wi ? W2 : W1;
        dofs = 98304 + (size_t)wi * 16384;
    }
    float x = src[(size_t)k * 128 + n];
    uint16_t h, l;
    split_bf16(x, h, l);
    size_t d = dofs + (size_t)n * K + k;
    ((uint16_t*)g_wh)[d] = h;
    ((uint16_t*)g_wl)[d] = l;
}

// ---------------- shared GEMM tile constants ------------------------------------
#define PADK 40                       // 80B row stride: 16B-aligned, ldmatrix conflict-free
#define MAT_BYTES (128 * PADK * 2)    // 10240
#define STAGE_BYTES (4 * MAT_BYTES)   // 40960
#define OFF_AH 0
#define OFF_AL MAT_BYTES
#define OFF_WH (2 * MAT_BYTES)
#define OFF_WL (3 * MAT_BYTES)
#define MLP_SMEM (2 * STAGE_BYTES + 20480)    // 102400

__device__ __forceinline__ void load_a_frags(uint32_t base_h, uint32_t base_l,
                                             int wm, int lane, int k0,
                                             uint32_t fah[4][4], uint32_t fal[4][4]) {
#pragma unroll
    for (int mi = 0; mi < 4; mi++) {
        uint32_t off = (uint32_t)((wm + mi * 16 + (lane & 15)) * PADK
                                  + k0 + ((lane >> 4) << 3)) * 2;
        ldmatrix_x4(fah[mi], base_h + off);
        ldmatrix_x4(fal[mi], base_l + off);
    }
}
__device__ __forceinline__ void load_b_frags(uint32_t base_h, uint32_t base_l,
                                             int wn, int lane, int k0,
                                             uint32_t fbh[4][2], uint32_t fbl[4][2]) {
#pragma unroll
    for (int njp = 0; njp < 2; njp++) {
        uint32_t off = (uint32_t)((wn + njp * 16 + ((lane >> 4) << 3) + (lane & 7)) * PADK
                                  + k0 + (((lane >> 3) & 1) << 3)) * 2;
        uint32_t t[4];
        ldmatrix_x4(t, base_h + off);
        fbh[2*njp][0] = t[0]; fbh[2*njp][1] = t[1];
        fbh[2*njp+1][0] = t[2]; fbh[2*njp+1][1] = t[3];
        ldmatrix_x4(t, base_l + off);
        fbl[2*njp][0] = t[0]; fbl[2*njp][1] = t[1];
        fbl[2*njp+1][0] = t[2]; fbl[2*njp+1][1] = t[3];
    }
}
__device__ __forceinline__ void mma_block(float acc[4][4][4],
                                          uint32_t fah[4][4], uint32_t fal[4][4],
                                          uint32_t fbh[4][2], uint32_t fbl[4][2]) {
#pragma unroll
    for (int mi = 0; mi < 4; mi++)
#pragma unroll
        for (int ni = 0; ni < 4; ni++) {
            mma_bf16(acc[mi][ni], fah[mi], fbh[ni]);
            mma_bf16(acc[mi][ni], fah[mi], fbl[ni]);
            mma_bf16(acc[mi][ni], fal[mi], fbh[ni]);
        }
}

// ---------------- A-resident fused QKV ------------------------------------------
// One CTA per 128-row block. Phase 1: X/STE fp32 -> split bf16 A tile [128x256]
// resident in smem (PADA=264 stride -> conflict-free ldmatrix). Phase 2: 24 flat
// stages (3 weights x 8 k-chunks), W double-buffered via cp.async, A frags from
// the resident tile. Epilogue per weight writes split-bf16 Q/K/V.
#define PADA 264
#define A_HI_OFF 0
#define A_LO_OFF (128 * PADA * 2)              // 67584
#define WST_OFF  (2 * 128 * PADA * 2)          // 135168
#define WST_STRIDE 20480                       // [Wh 10240 | Wl 10240]
#define QKVF_SMEM (WST_OFF + 2 * WST_STRIDE)   // 176128

__global__ __launch_bounds__(256)
void qkv_fused(const float* __restrict__ X, const float* __restrict__ STE,
               const float* __restrict__ bq, const float* __restrict__ bk,
               const float* __restrict__ bv)
{
    extern __shared__ __align__(16) char smem[];
    const uint32_t sb = smem_u32(smem);
    const int tid  = threadIdx.x;
    const int lane = tid & 31;
    const int wid  = tid >> 5;
    const int wm   = (wid & 1) * 64;
    const int wn   = (wid >> 1) * 32;
    const int row0 = blockIdx.x * 128;

    // ---- phase 1: load fp32 concat(X,STE), split, store resident A tile ----
#pragma unroll
    for (int i = 0; i < 16; i++) {
        int id = tid + i * 256;          // 0..4095 (8-elem chunks)
        int r  = id >> 5;
        int c8 = (id & 31) * 8;
        const float* src = (c8 < 128) ? X + (size_t)(row0 + r) * 128 + c8
                                      : STE + (size_t)(row0 + r) * 128 + (c8 - 128);
        float4 f0 = ((const float4*)src)[0];
        float4 f1 = ((const float4*)src)[1];
        float v[8] = {f0.x, f0.y, f0.z, f0.w, f1.x, f1.y, f1.z, f1.w};
        uint32_t hp[4], lp[4];
#pragma unroll
        for (int j = 0; j < 4; j++) split2(v[2*j], v[2*j+1], hp[j], lp[j]);
        uint32_t off = (uint32_t)(r * PADA + c8) * 2;
        asm volatile("st.shared.v4.b32 [%0], {%1,%2,%3,%4};"
                     :: "r"(sb + A_HI_OFF + off), "r"(hp[0]), "r"(hp[1]), "r"(hp[2]), "r"(hp[3]) : "memory");
        asm volatile("st.shared.v4.b32 [%0], {%1,%2,%3,%4};"
                     :: "r"(sb + A_LO_OFF + off), "r"(lp[0]), "r"(lp[1]), "r"(lp[2]), "r"(lp[3]) : "memory");
    }

    // ---- W stage loader (chunk = [128 n][32 k] hi+lo) ----
    const int c0 = tid * 2;
    const int lr0 = c0 >> 2,        lc0 = (c0 & 3) << 3;
    const int lr1 = (c0 + 1) >> 2,  lc1 = ((c0 + 1) & 3) << 3;
    auto load_w = [&](int wsel, int kt, int buf) {
        const __nv_bfloat16* Wh = g_wh + wsel * 32768;
        const __nv_bfloat16* Wl = g_wl + wsel * 32768;
        uint32_t s = sb + WST_OFF + buf * WST_STRIDE;
        uint32_t d0 = (uint32_t)(lr0 * PADK + lc0) * 2;
        uint32_t d1 = (uint32_t)(lr1 * PADK + lc1) * 2;
        size_t gW0 = (size_t)lr0 * 256 + kt + lc0;
        size_t gW1 = (size_t)lr1 * 256 + kt + lc1;
        cp_async16(s + d0,         Wh + gW0);
        cp_async16(s + d1,         Wh + gW1);
        cp_async16(s + 10240 + d0, Wl + gW0);
        cp_async16(s + 10240 + d1, Wl + gW1);
    };

    float acc[4][4][4];
#pragma unroll
    for (int i = 0; i < 4; i++)
#pragma unroll
        for (int j = 0; j < 4; j++)
#pragma unroll
            for (int r = 0; r < 4; r++) acc[i][j][r] = 0.f;

    load_w(0, 0, 0);
    cp_commit();

    // ---- phase 2: 24 flat stages ----
    for (int st = 0; st < 24; st++) {
        cp_wait0();
        __syncthreads();   // stage st visible; all warps done with st-1 (A stores on st=0)
        if (st + 1 < 24) {
            load_w((st + 1) >> 3, ((st + 1) & 7) * 32, (st + 1) & 1);
            cp_commit();
        }
        const uint32_t wbase = sb + WST_OFF + (st & 1) * WST_STRIDE;
        const int kt = (st & 7) * 32;
#pragma unroll
        for (int ks = 0; ks < 2; ks++) {
            const int k0a = kt + ks * 16;
            uint32_t fah[4][4], fal[4][4];
#pragma unroll
            for (int mi = 0; mi < 4; mi++) {
                uint32_t off = (uint32_t)((wm + mi * 16 + (lane & 15)) * PADA
                                          + k0a + ((lane >> 4) << 3)) * 2;
                ldmatrix_x4(fah[mi], sb + A_HI_OFF + off);
                ldmatrix_x4(fal[mi], sb + A_LO_OFF + off);
            }
            uint32_t fbh[4][2], fbl[4][2];
            load_b_frags(wbase, wbase + 10240, wn, lane, ks * 16, fbh, fbl);
            mma_block(acc, fah, fal, fbh, fbl);
        }

        if ((st & 7) == 7) {
            const int wsel = st >> 3;
            const float* __restrict__ bias = (wsel == 0) ? bq : (wsel == 1) ? bk : bv;
            uint16_t* __restrict__ oh = (uint16_t*)((wsel == 0) ? g_q_hi : (wsel == 1) ? g_k_hi : g_v_hi);
            uint16_t* __restrict__ ol = (uint16_t*)((wsel == 0) ? g_q_lo : (wsel == 1) ? g_k_lo : g_v_lo);
#pragma unroll
            for (int mi = 0; mi < 4; mi++) {
#pragma unroll
                for (int ni = 0; ni < 4; ni++) {
                    int r0 = row0 + wm + mi * 16 + (lane >> 2);
                    int c  = wn + ni * 8 + ((lane & 3) << 1);
                    float b0 = bias[c], b1 = bias[c + 1];
                    float v00 = fmaxf(acc[mi][ni][0] + b0, 0.f), v01 = fmaxf(acc[mi][ni][1] + b1, 0.f);
                    float v10 = fmaxf(acc[mi][ni][2] + b0, 0.f), v11 = fmaxf(acc[mi][ni][3] + b1, 0.f);
                    uint32_t hi, lo;
                    split2(v00, v01, hi, lo);
                    *(uint32_t*)(oh + (size_t)r0 * 128 + c) = hi;
                    *(uint32_t*)(ol + (size_t)r0 * 128 + c) = lo;
                    split2(v10, v11, hi, lo);
                    *(uint32_t*)(oh + (size_t)(r0 + 8) * 128 + c) = hi;
                    *(uint32_t*)(ol + (size_t)(r0 + 8) * 128 + c) = lo;
                    acc[mi][ni][0] = 0.f; acc[mi][ni][1] = 0.f;
                    acc[mi][ni][2] = 0.f; acc[mi][ni][3] = 0.f;
                }
            }
        }
    }
}

// ---------------- fused MLP (unchanged from R9/R12) -------------------------------
__global__ __launch_bounds__(256)
void mlp_fused(const float* __restrict__ b1, const float* __restrict__ b2,
               float* __restrict__ out)
{
    extern __shared__ __align__(16) char smem[];
    const uint32_t sb = smem_u32(smem);

    const __nv_bfloat16* __restrict__ Ah = g_att_hi;
    const __nv_bfloat16* __restrict__ Al = g_att_lo;
    const __nv_bfloat16* __restrict__ W1h = g_wh + 98304;
    const __nv_bfloat16* __restrict__ W1l = g_wl + 98304;
    const __nv_bfloat16* __restrict__ W2h = g_wh + 114688;
    const __nv_bfloat16* __restrict__ W2l = g_wl + 114688;

    const int tid  = threadIdx.x;
    const int lane = tid & 31;
    const int wid  = tid >> 5;
    const int wm   = (wid & 1) * 64;
    const int wn   = (wid >> 1) * 32;
    const int row0 = blockIdx.x * 128;

    const int c0 = tid * 2;
    const int lr0 = c0 >> 2,        lc0 = (c0 & 3) << 3;
    const int lr1 = (c0 + 1) >> 2,  lc1 = ((c0 + 1) & 3) << 3;

    float acc[4][4][4];
#pragma unroll
    for (int i = 0; i < 4; i++)
#pragma unroll
        for (int j = 0; j < 4; j++)
#pragma unroll
            for (int r = 0; r < 4; r++) acc[i][j][r] = 0.f;

    auto load_stage1 = [&](int kt, int buf) {
        uint32_t s = sb + buf * STAGE_BYTES;
        uint32_t d0 = (uint32_t)(lr0 * PADK + lc0) * 2;
        uint32_t d1 = (uint32_t)(lr1 * PADK + lc1) * 2;
        size_t gA0 = (size_t)(row0 + lr0) * 128 + kt + lc0;
        size_t gA1 = (size_t)(row0 + lr1) * 128 + kt + lc1;
        size_t gW0 = (size_t)lr0 * 128 + kt + lc0;
        size_t gW1 = (size_t)lr1 * 128 + kt + lc1;
        cp_async16(s + OFF_AH + d0, Ah + gA0);
        cp_async16(s + OFF_AH + d1, Ah + gA1);
        cp_async16(s + OFF_AL + d0, Al + gA0);
        cp_async16(s + OFF_AL + d1, Al + gA1);
        cp_async16(s + OFF_WH + d0, W1h + gW0);
        cp_async16(s + OFF_WH + d1, W1h + gW1);
        cp_async16(s + OFF_WL + d0, W1l + gW0);
        cp_async16(s + OFF_WL + d1, W1l + gW1);
    };

    load_stage1(0, 0);
    cp_commit();
    for (int s = 0; s < 4; s++) {
        cp_wait0();
        __syncthreads();
        if (s + 1 < 4) { load_stage1((s + 1) * 32, (s + 1) & 1); cp_commit(); }
        const uint32_t base = sb + (s & 1) * STAGE_BYTES;
#pragma unroll
        for (int ks = 0; ks < 2; ks++) {
            const int k0 = ks * 16;
            uint32_t fah[4][4], fal[4][4], fbh[4][2], fbl[4][2];
            load_a_frags(base + OFF_AH, base + OFF_AL, wm, lane, k0, fah, fal);
            load_b_frags(base + OFF_WH, base + OFF_WL, wn, lane, k0, fbh, fbl);
            mma_block(acc, fah, fal, fbh, fbl);
        }
    }
    __syncthreads();

#pragma unroll
    for (int mi = 0; mi < 4; mi++) {
#pragma unroll
        for (int ni = 0; ni < 4; ni++) {
            int r  = wm + mi * 16 + (lane >> 2);
            int c  = wn + ni * 8 + ((lane & 3) << 1);
            int kc = c >> 5, cc = c & 31;
            uint32_t hbase = sb + (uint32_t)kc * (2 * MAT_BYTES);
            float b0 = b1[c], bb1 = b1[c + 1];
            float v00 = fmaxf(acc[mi][ni][0] + b0, 0.f), v01 = fmaxf(acc[mi][ni][1] + bb1, 0.f);
            float v10 = fmaxf(acc[mi][ni][2] + b0, 0.f), v11 = fmaxf(acc[mi][ni][3] + bb1, 0.f);
            uint32_t hi, lo;
            split2(v00, v01, hi, lo);
            asm volatile("st.shared.b32 [%0], %1;" :: "r"(hbase + (uint32_t)(r * PADK + cc) * 2), "r"(hi) : "memory");
            asm volatile("st.shared.b32 [%0], %1;" :: "r"(hbase + MAT_BYTES + (uint32_t)(r * PADK + cc) * 2), "r"(lo) : "memory");
            split2(v10, v11, hi, lo);
            asm volatile("st.shared.b32 [%0], %1;" :: "r"(hbase + (uint32_t)((r + 8) * PADK + cc) * 2), "r"(hi) : "memory");
            asm volatile("st.shared.b32 [%0], %1;" :: "r"(hbase + MAT_BYTES + (uint32_t)((r + 8) * PADK + cc) * 2), "r"(lo) : "memory");
        }
    }

#pragma unroll
    for (int i = 0; i < 4; i++)
#pragma unroll
        for (int j = 0; j < 4; j++)
#pragma unroll
            for (int r = 0; r < 4; r++) acc[i][j][r] = 0.f;

    const uint32_t w2base = sb + 2 * STAGE_BYTES;
    for (int kc = 0; kc < 4; kc++) {
        {
            uint32_t d0 = (uint32_t)(lr0 * PADK + lc0) * 2;
            uint32_t d1 = (uint32_t)(lr1 * PADK + lc1) * 2;
            size_t gW0 = (size_t)lr0 * 128 + kc * 32 + lc0;
            size_t gW1 = (size_t)lr1 * 128 + kc * 32 + lc1;
            cp_async16(w2base + d0,             W2h + gW0);
            cp_async16(w2base + d1,             W2h + gW1);
            cp_async16(w2base + MAT_BYTES + d0, W2l + gW0);
            cp_async16(w2base + MAT_BYTES + d1, W2l + gW1);
        }
        cp_commit();
        cp_wait0();
        __syncthreads();

        const uint32_t hbase = sb + (uint32_t)kc * (2 * MAT_BYTES);
#pragma unroll
        for (int ks = 0; ks < 2; ks++) {
            const int k0 = ks * 16;
            uint32_t fah[4][4], fal[4][4], fbh[4][2], fbl[4][2];
            load_a_frags(hbase, hbase + MAT_BYTES, wm, lane, k0, fah, fal);
            load_b_frags(w2base, w2base + MAT_BYTES, wn, lane, k0, fbh, fbl);
            mma_block(acc, fah, fal, fbh, fbl);
        }
        __syncthreads();
    }

#pragma unroll
    for (int mi = 0; mi < 4; mi++) {
#pragma unroll
        for (int ni = 0; ni < 4; ni++) {
            int r0 = row0 + wm + mi * 16 + (lane >> 2);
            int c  = wn + ni * 8 + ((lane & 3) << 1);
            float b0 = b2[c], bb1 = b2[c + 1];
            *(float2*)&out[(size_t)r0 * 128 + c] =
                make_float2(acc[mi][ni][0] + b0, acc[mi][ni][1] + bb1);
            *(float2*)&out[(size_t)(r0 + 8) * 128 + c] =
                make_float2(acc[mi][ni][2] + b0, acc[mi][ni][3] + bb1);
        }
    }
}

// ---------------- split-K scalar attention (unchanged from R12) -------------------
__global__ __launch_bounds__(256)
void attn_scalar()
{
    const int n  = blockIdx.x;
    const int bh = blockIdx.y;
    const int b  = bh >> 3;
    const int h  = bh & 7;
    const int tid = threadIdx.x;
    const int t  = tid >> 1;          // query row
    const int u  = tid & 1;           // key-parity half

    __shared__ float Ks[128][16];
    __shared__ float Vs[128][16];

    const size_t base = ((size_t)(b * P_) * N_ + n) * D_ + h * 16;

    // ---- stage K/V ----
    {
        int r = tid >> 1, cs = (tid & 1) * 8;
        size_t off = base + (size_t)r * ROWSTRIDE_ + cs;
        uint4 KH = *(const uint4*)((const uint16_t*)g_k_hi + off);
        uint4 KL = *(const uint4*)((const uint16_t*)g_k_lo + off);
        uint4 VH = *(const uint4*)((const uint16_t*)g_v_hi + off);
        uint4 VL = *(const uint4*)((const uint16_t*)g_v_lo + off);
        const uint16_t* kh = (const uint16_t*)&KH;
        const uint16_t* kl = (const uint16_t*)&KL;
        const uint16_t* vh = (const uint16_t*)&VH;
        const uint16_t* vl = (const uint16_t*)&VL;
        float kf[8], vf[8];
#pragma unroll
        for (int i = 0; i < 8; i++) {
            kf[i] = join_bf16(kh[i], kl[i]);
            vf[i] = join_bf16(vh[i], vl[i]);
        }
        *(float4*)&Ks[r][cs]     = make_float4(kf[0], kf[1], kf[2], kf[3]);
        *(float4*)&Ks[r][cs + 4] = make_float4(kf[4], kf[5], kf[6], kf[7]);
        *(float4*)&Vs[r][cs]     = make_float4(vf[0], vf[1], vf[2], vf[3]);
        *(float4*)&Vs[r][cs + 4] = make_float4(vf[4], vf[5], vf[6], vf[7]);
    }

    // ---- Q row t ----
    float qr[16];
    {
        size_t off = base + (size_t)t * ROWSTRIDE_;
        uint4 H0 = *(const uint4*)((const uint16_t*)g_q_hi + off);
        uint4 H1 = *(const uint4*)((const uint16_t*)g_q_hi + off + 8);
        uint4 L0 = *(const uint4*)((const uint16_t*)g_q_lo + off);
        uint4 L1 = *(const uint4*)((const uint16_t*)g_q_lo + off + 8);
        const uint16_t* h0 = (const uint16_t*)&H0;
        const uint16_t* h1 = (const uint16_t*)&H1;
        const uint16_t* l0 = (const uint16_t*)&L0;
        const uint16_t* l1 = (const uint16_t*)&L1;
#pragma unroll
        for (int i = 0; i < 8; i++) {
            qr[i]     = join_bf16(h0[i], l0[i]);
            qr[i + 8] = join_bf16(h1[i], l1[i]);
        }
    }
    __syncthreads();

    // ---- online softmax over keys of parity u ----
    float m = -1e30f, denom = 0.f;
    float o[16];
#pragma unroll
    for (int d = 0; d < 16; d++) o[d] = 0.f;

    for (int q = u; q <= t; q += 2) {
        float4 k0 = *(const float4*)&Ks[q][0];
        float4 k1 = *(const float4*)&Ks[q][4];
        float4 k2 = *(const float4*)&Ks[q][8];
        float4 k3 = *(const float4*)&Ks[q][12];
        float s = qr[0] * k0.x;
        s = fmaf(qr[1],  k0.y, s); s = fmaf(qr[2],  k0.z, s); s = fmaf(qr[3],  k0.w, s);
        s = fmaf(qr[4],  k1.x, s); s = fmaf(qr[5],  k1.y, s); s = fmaf(qr[6],  k1.z, s); s = fmaf(qr[7],  k1.w, s);
        s = fmaf(qr[8],  k2.x, s); s = fmaf(qr[9],  k2.y, s); s = fmaf(qr[10], k2.z, s); s = fmaf(qr[11], k2.w, s);
        s = fmaf(qr[12], k3.x, s); s = fmaf(qr[13], k3.y, s); s = fmaf(qr[14], k3.z, s); s = fmaf(qr[15], k3.w, s);
        s *= 0.25f;   // 1/sqrt(d_head=16)

        if (s > m) {
            float scale = __expf(m - s);
            denom *= scale;
#pragma unroll
            for (int d = 0; d < 16; d++) o[d] *= scale;
            m = s;
        }
        float w = __expf(s - m);
        denom += w;

        float4 v0 = *(const float4*)&Vs[q][0];
        float4 v1 = *(const float4*)&Vs[q][4];
        float4 v2 = *(const float4*)&Vs[q][8];
        float4 v3 = *(const float4*)&Vs[q][12];
        o[0]  = fmaf(w, v0.x, o[0]);  o[1]  = fmaf(w, v0.y, o[1]);
        o[2]  = fmaf(w, v0.z, o[2]);  o[3]  = fmaf(w, v0.w, o[3]);
        o[4]  = fmaf(w, v1.x, o[4]);  o[5]  = fmaf(w, v1.y, o[5]);
        o[6]  = fmaf(w, v1.z, o[6]);  o[7]  = fmaf(w, v1.w, o[7]);
        o[8]  = fmaf(w, v2.x, o[8]);  o[9]  = fmaf(w, v2.y, o[9]);
        o[10] = fmaf(w, v2.z, o[10]); o[11] = fmaf(w, v2.w, o[11]);
        o[12] = fmaf(w, v3.x, o[12]); o[13] = fmaf(w, v3.y, o[13]);
        o[14] = fmaf(w, v3.z, o[14]); o[15] = fmaf(w, v3.w, o[15]);
    }

    // ---- merge the two parity-halves ----
    float m2 = __shfl_xor_sync(0xffffffffu, m, 1);
    float d2 = __shfl_xor_sync(0xffffffffu, denom, 1);
    float M  = fmaxf(m, m2);
    float sa = __expf(m - M);
    float sb_ = __expf(m2 - M);
    float D  = denom * sa + d2 * sb_;
    float inv = 1.f / D;

    float val[16];
#pragma unroll
    for (int d = 0; d < 16; d++) {
        float oo = __shfl_xor_sync(0xffffffffu, o[d], 1);
        val[d] = (o[d] * sa + oo * sb_) * inv;
    }

    if (u == 0) {
        size_t ob = base + (size_t)t * ROWSTRIDE_;
        uint32_t hp[8], lp[8];
#pragma unroll
        for (int j = 0; j < 8; j++)
            split2(val[2 * j], val[2 * j + 1], hp[j], lp[j]);
        *(uint4*)((uint16_t*)g_att_hi + ob)     = make_uint4(hp[0], hp[1], hp[2], hp[3]);
        *(uint4*)((uint16_t*)g_att_hi + ob + 8) = make_uint4(hp[4], hp[5], hp[6], hp[7]);
        *(uint4*)((uint16_t*)g_att_lo + ob)     = make_uint4(lp[0], lp[1], lp[2], lp[3]);
        *(uint4*)((uint16_t*)g_att_lo + ob + 8) = make_uint4(lp[4], lp[5], lp[6], lp[7]);
    }
}

// ---------------- launch -------------------------------------------------------
extern "C" void kernel_launch(void* const* d_in, const int* in_sizes, int n_in,
                              void* d_out, int out_size)
{
    const float* X   = (const float*)d_in[0];
    const float* STE = (const float*)d_in[1];
    const float* Wq  = (const float*)d_in[2];
    const float* bq  = (const float*)d_in[3];
    const float* Wk  = (const float*)d_in[4];
    const float* bk  = (const float*)d_in[5];
    const float* Wv  = (const float*)d_in[6];
    const float* bv  = (const float*)d_in[7];
    const float* W1  = (const float*)d_in[8];
    const float* b1  = (const float*)d_in[9];
    const float* W2  = (const float*)d_in[10];
    const float* b2  = (const float*)d_in[11];
    float* out = (float*)d_out;

    cudaFuncSetAttribute(qkv_fused, cudaFuncAttributeMaxDynamicSharedMemorySize, QKVF_SMEM);
    cudaFuncSetAttribute(mlp_fused, cudaFuncAttributeMaxDynamicSharedMemorySize, MLP_SMEM);

    // weight preprocessing (transpose + bf16 split)
    convert_w<<<512, 256>>>(Wq, Wk, Wv, W1, W2);

    // A-resident fused QKV projections (reads X/STE fp32 directly)
    qkv_fused<<<M_ / 128, 256, QKVF_SMEM>>>(X, STE, bq, bk, bv);

    // split-K scalar attention: block per (b, head, node)
    attn_scalar<<<dim3(N_, B_ * 8), 256>>>();

    // fused output MLP
    mlp_fused<<<M_ / 128, 256, MLP_SMEM>>>(b1, b2, out);
}

// round 14
// speedup vs baseline: 1.3242x; 1.3242x over previous
#include <cuda_runtime.h>
#include <cuda_bf16.h>
#include <math.h>
#include <stdint.h>

#define B_   8
#define P_   128
#define N_   256
#define D_   128
#define M_   (B_*P_*N_)        // 262144 rows
#define ROWSTRIDE_ 32768       // N_*D_ elements between consecutive p for fixed (b,n)

// ---------------- scratch (device globals; no allocation allowed) ----------------
__device__ __align__(16) __nv_bfloat16 g_a_hi[(size_t)M_ * 256];
__device__ __align__(16) __nv_bfloat16 g_a_lo[(size_t)M_ * 256];
__device__ __align__(16) __nv_bfloat16 g_q_hi[(size_t)M_ * D_];
__device__ __align__(16) __nv_bfloat16 g_q_lo[(size_t)M_ * D_];
__device__ __align__(16) __nv_bfloat16 g_k_hi[(size_t)M_ * D_];
__device__ __align__(16) __nv_bfloat16 g_k_lo[(size_t)M_ * D_];
__device__ __align__(16) __nv_bfloat16 g_v_hi[(size_t)M_ * D_];
__device__ __align__(16) __nv_bfloat16 g_v_lo[(size_t)M_ * D_];
__device__ __align__(16) __nv_bfloat16 g_att_hi[(size_t)M_ * D_];
__device__ __align__(16) __nv_bfloat16 g_att_lo[(size_t)M_ * D_];
// weights transposed to [n][k], bf16-split. layout: Wq(32768) Wk Wv W1(16384) W2
__device__ __align__(16) __nv_bfloat16 g_wh[131072];
__device__ __align__(16) __nv_bfloat16 g_wl[131072];

// ---------------- helpers ----------------
__device__ __forceinline__ uint32_t smem_u32(const void* p) {
    uint32_t a;
    asm("{ .reg .u64 t; cvta.to.shared.u64 t, %1; cvt.u32.u64 %0, t; }" : "=r"(a) : "l"(p));
    return a;
}
__device__ __forceinline__ void split_bf16(float x, uint16_t& h, uint16_t& l) {
    __nv_bfloat16 hb = __float2bfloat16(x);
    __nv_bfloat16 lb = __float2bfloat16(x - __bfloat162float(hb));
    h = __bfloat16_as_ushort(hb);
    l = __bfloat16_as_ushort(lb);
}
__device__ __forceinline__ void split2(float a, float b, uint32_t& hi, uint32_t& lo) {
    uint16_t ha, la, hb, lb;
    split_bf16(a, ha, la);
    split_bf16(b, hb, lb);
    hi = (uint32_t)ha | ((uint32_t)hb << 16);
    lo = (uint32_t)la | ((uint32_t)lb << 16);
}
__device__ __forceinline__ float ex2f(float x) {
    float y; asm("ex2.approx.f32 %0, %1;" : "=f"(y) : "f"(x)); return y;
}
__device__ __forceinline__ void ldmatrix_x4(uint32_t* r, uint32_t addr) {
    asm volatile("ldmatrix.sync.aligned.m8n8.x4.shared.b16 {%0,%1,%2,%3}, [%4];"
                 : "=r"(r[0]), "=r"(r[1]), "=r"(r[2]), "=r"(r[3]) : "r"(addr));
}
__device__ __forceinline__ void ldmatrix_x4t(uint32_t* r, uint32_t addr) {
    asm volatile("ldmatrix.sync.aligned.m8n8.x4.trans.shared.b16 {%0,%1,%2,%3}, [%4];"
                 : "=r"(r[0]), "=r"(r[1]), "=r"(r[2]), "=r"(r[3]) : "r"(addr));
}
__device__ __forceinline__ void mma_bf16(float* d, const uint32_t* a, const uint32_t* b) {
    asm volatile(
        "mma.sync.aligned.m16n8k16.row.col.f32.bf16.bf16.f32 "
        "{%0,%1,%2,%3}, {%4,%5,%6,%7}, {%8,%9}, {%0,%1,%2,%3};"
        : "+f"(d[0]), "+f"(d[1]), "+f"(d[2]), "+f"(d[3])
        : "r"(a[0]), "r"(a[1]), "r"(a[2]), "r"(a[3]), "r"(b[0]), "r"(b[1]));
}
__device__ __forceinline__ void cp_async16(uint32_t dst, const void* src) {
    asm volatile("cp.async.cg.shared.global [%0], [%1], 16;" :: "r"(dst), "l"(src));
}
__device__ __forceinline__ void cp_commit() {
    asm volatile("cp.async.commit_group;" ::: "memory");
}
__device__ __forceinline__ void cp_wait0() {
    asm volatile("cp.async.wait_group 0;" ::: "memory");
}

// ---------------- convert weights: W[k][n] fp32 -> transposed split bf16 ----------
__global__ void convert_w(const float* __restrict__ Wq, const float* __restrict__ Wk,
                          const float* __restrict__ Wv, const float* __restrict__ W1,
                          const float* __restrict__ W2)
{
    int id = blockIdx.x * 256 + threadIdx.x;      // < 131072
    const float* src; int K, n, k; size_t dofs;
    if (id < 98304) {
        int wi = id >> 15, rem = id & 32767;
        k = rem >> 7; n = rem & 127; K = 256;
        src = (wi == 0) ? Wq : (wi == 1) ? Wk : Wv;
        dofs = (size_t)wi * 32768;
    } else {
        int r2 = id - 98304;
        int wi = r2 >> 14, rem = r2 & 16383;
        k = rem >> 7; n = rem & 127; K = 128;
        src = wi ? W2 : W1;
        dofs = 98304 + (size_t)wi * 16384;
    }
    float x = src[(size_t)k * 128 + n];
    uint16_t h, l;
    split_bf16(x, h, l);
    size_t d = dofs + (size_t)n * K + k;
    ((uint16_t*)g_wh)[d] = h;
    ((uint16_t*)g_wl)[d] = l;
}

// ---------------- convert activations: concat(X,STE) -> split bf16 [M x 256] -----
__global__ void convert_a(const float* __restrict__ X, const float* __restrict__ STE)
{
    size_t id = (size_t)blockIdx.x * 256 + threadIdx.x;   // one per 8 elements
    int row = (int)(id >> 5);
    int c8  = (int)(id & 31) << 3;
    const float* src = (c8 < 128) ? (X + (size_t)row * 128 + c8)
                                  : (STE + (size_t)row * 128 + (c8 - 128));
    float4 v0 = ((const float4*)src)[0];
    float4 v1 = ((const float4*)src)[1];
    float vv[8] = {v0.x, v0.y, v0.z, v0.w, v1.x, v1.y, v1.z, v1.w};
    uint32_t hp[4], lp[4];
#pragma unroll
    for (int j = 0; j < 4; j++)
        split2(vv[2 * j], vv[2 * j + 1], hp[j], lp[j]);
    size_t e = (size_t)row * 256 + c8;
    *(uint4*)((uint16_t*)g_a_hi + e) = make_uint4(hp[0], hp[1], hp[2], hp[3]);
    *(uint4*)((uint16_t*)g_a_lo + e) = make_uint4(lp[0], lp[1], lp[2], lp[3]);
}

// ---------------- shared GEMM tile constants ------------------------------------
#define PADK 40                       // 80B row stride: 16B-aligned, ldmatrix conflict-free
#define MAT_BYTES (128 * PADK * 2)    // 10240
#define STAGE_BYTES (4 * MAT_BYTES)   // 40960
#define OFF_AH 0
#define OFF_AL MAT_BYTES
#define OFF_WH (2 * MAT_BYTES)
#define OFF_WL (3 * MAT_BYTES)
#define QKV_SMEM (2 * STAGE_BYTES)            // 81920
#define MLP_SMEM (2 * STAGE_BYTES + 20480)    // 102400

__device__ __forceinline__ void load_a_frags(uint32_t base_h, uint32_t base_l,
                                             int wm, int lane, int k0,
                                             uint32_t fah[4][4], uint32_t fal[4][4]) {
#pragma unroll
    for (int mi = 0; mi < 4; mi++) {
        uint32_t off = (uint32_t)((wm + mi * 16 + (lane & 15)) * PADK
                                  + k0 + ((lane >> 4) << 3)) * 2;
        ldmatrix_x4(fah[mi], base_h + off);
        ldmatrix_x4(fal[mi], base_l + off);
    }
}
__device__ __forceinline__ void load_b_frags(uint32_t base_h, uint32_t base_l,
                                             int wn, int lane, int k0,
                                             uint32_t fbh[4][2], uint32_t fbl[4][2]) {
#pragma unroll
    for (int njp = 0; njp < 2; njp++) {
        uint32_t off = (uint32_t)((wn + njp * 16 + ((lane >> 4) << 3) + (lane & 7)) * PADK
                                  + k0 + (((lane >> 3) & 1) << 3)) * 2;
        uint32_t t[4];
        ldmatrix_x4(t, base_h + off);
        fbh[2*njp][0] = t[0]; fbh[2*njp][1] = t[1];
        fbh[2*njp+1][0] = t[2]; fbh[2*njp+1][1] = t[3];
        ldmatrix_x4(t, base_l + off);
        fbl[2*njp][0] = t[0]; fbl[2*njp][1] = t[1];
        fbl[2*njp+1][0] = t[2]; fbl[2*njp+1][1] = t[3];
    }
}
__device__ __forceinline__ void mma_block(float acc[4][4][4],
                                          uint32_t fah[4][4], uint32_t fal[4][4],
                                          uint32_t fbh[4][2], uint32_t fbl[4][2]) {
#pragma unroll
    for (int mi = 0; mi < 4; mi++)
#pragma unroll
        for (int ni = 0; ni < 4; ni++) {
            mma_bf16(acc[mi][ni], fah[mi], fbh[ni]);
            mma_bf16(acc[mi][ni], fah[mi], fbl[ni]);
            mma_bf16(acc[mi][ni], fal[mi], fbh[ni]);
        }
}

// ---------------- fused QKV GEMM (split-bf16 epilogue) ----------------------------
__global__ __launch_bounds__(256)
void qkv_gemm(const float* __restrict__ bq, const float* __restrict__ bk,
              const float* __restrict__ bv)
{
    extern __shared__ __align__(16) char smem[];
    const uint32_t sb = smem_u32(smem);

    const int wsel = blockIdx.x;
    const int row0 = blockIdx.y * 128;
    const __nv_bfloat16* __restrict__ Ah = g_a_hi;
    const __nv_bfloat16* __restrict__ Al = g_a_lo;
    const __nv_bfloat16* __restrict__ Wh = g_wh + wsel * 32768;
    const __nv_bfloat16* __restrict__ Wl = g_wl + wsel * 32768;
    const float* __restrict__ bias = (wsel == 0) ? bq : (wsel == 1) ? bk : bv;
    uint16_t* __restrict__ oh = (uint16_t*)((wsel == 0) ? g_q_hi : (wsel == 1) ? g_k_hi : g_v_hi);
    uint16_t* __restrict__ ol = (uint16_t*)((wsel == 0) ? g_q_lo : (wsel == 1) ? g_k_lo : g_v_lo);

    const int tid  = threadIdx.x;
    const int lane = tid & 31;
    const int wid  = tid >> 5;
    const int wm   = (wid & 1) * 64;
    const int wn   = (wid >> 1) * 32;

    float acc[4][4][4];
#pragma unroll
    for (int i = 0; i < 4; i++)
#pragma unroll
        for (int j = 0; j < 4; j++)
#pragma unroll
            for (int r = 0; r < 4; r++) acc[i][j][r] = 0.f;

    const int c0 = tid * 2;
    const int lr0 = c0 >> 2,        lc0 = (c0 & 3) << 3;
    const int lr1 = (c0 + 1) >> 2,  lc1 = ((c0 + 1) & 3) << 3;

    auto load_stage = [&](int kt, int buf) {
        uint32_t s = sb + buf * STAGE_BYTES;
        uint32_t d0 = (uint32_t)(lr0 * PADK + lc0) * 2;
        uint32_t d1 = (uint32_t)(lr1 * PADK + lc1) * 2;
        size_t gA0 = (size_t)(row0 + lr0) * 256 + kt + lc0;
        size_t gA1 = (size_t)(row0 + lr1) * 256 + kt + lc1;
        size_t gW0 = (size_t)lr0 * 256 + kt + lc0;
        size_t gW1 = (size_t)lr1 * 256 + kt + lc1;
        cp_async16(s + OFF_AH + d0, Ah + gA0);
        cp_async16(s + OFF_AH + d1, Ah + gA1);
        cp_async16(s + OFF_AL + d0, Al + gA0);
        cp_async16(s + OFF_AL + d1, Al + gA1);
        cp_async16(s + OFF_WH + d0, Wh + gW0);
        cp_async16(s + OFF_WH + d1, Wh + gW1);
        cp_async16(s + OFF_WL + d0, Wl + gW0);
        cp_async16(s + OFF_WL + d1, Wl + gW1);
    };

    const int NS = 8;
    load_stage(0, 0);
    cp_commit();

    for (int s = 0; s < NS; s++) {
        cp_wait0();
        __syncthreads();
        if (s + 1 < NS) { load_stage((s + 1) * 32, (s + 1) & 1); cp_commit(); }

        const uint32_t base = sb + (s & 1) * STAGE_BYTES;
#pragma unroll
        for (int ks = 0; ks < 2; ks++) {
            const int k0 = ks * 16;
            uint32_t fah[4][4], fal[4][4], fbh[4][2], fbl[4][2];
            load_a_frags(base + OFF_AH, base + OFF_AL, wm, lane, k0, fah, fal);
            load_b_frags(base + OFF_WH, base + OFF_WL, wn, lane, k0, fbh, fbl);
            mma_block(acc, fah, fal, fbh, fbl);
        }
    }

#pragma unroll
    for (int mi = 0; mi < 4; mi++) {
#pragma unroll
        for (int ni = 0; ni < 4; ni++) {
            int r0 = row0 + wm + mi * 16 + (lane >> 2);
            int c  = wn + ni * 8 + ((lane & 3) << 1);
            float b0 = bias[c], b1 = bias[c + 1];
            float v00 = fmaxf(acc[mi][ni][0] + b0, 0.f), v01 = fmaxf(acc[mi][ni][1] + b1, 0.f);
            float v10 = fmaxf(acc[mi][ni][2] + b0, 0.f), v11 = fmaxf(acc[mi][ni][3] + b1, 0.f);
            uint32_t hi, lo;
            split2(v00, v01, hi, lo);
            *(uint32_t*)(oh + (size_t)r0 * 128 + c) = hi;
            *(uint32_t*)(ol + (size_t)r0 * 128 + c) = lo;
            split2(v10, v11, hi, lo);
            *(uint32_t*)(oh + (size_t)(r0 + 8) * 128 + c) = hi;
            *(uint32_t*)(ol + (size_t)(r0 + 8) * 128 + c) = lo;
        }
    }
}

// ---------------- fused MLP (unchanged) ------------------------------------------
__global__ __launch_bounds__(256)
void mlp_fused(const float* __restrict__ b1, const float* __restrict__ b2,
               float* __restrict__ out)
{
    extern __shared__ __align__(16) char smem[];
    const uint32_t sb = smem_u32(smem);

    const __nv_bfloat16* __restrict__ Ah = g_att_hi;
    const __nv_bfloat16* __restrict__ Al = g_att_lo;
    const __nv_bfloat16* __restrict__ W1h = g_wh + 98304;
    const __nv_bfloat16* __restrict__ W1l = g_wl + 98304;
    const __nv_bfloat16* __restrict__ W2h = g_wh + 114688;
    const __nv_bfloat16* __restrict__ W2l = g_wl + 114688;

    const int tid  = threadIdx.x;
    const int lane = tid & 31;
    const int wid  = tid >> 5;
    const int wm   = (wid & 1) * 64;
    const int wn   = (wid >> 1) * 32;
    const int row0 = blockIdx.x * 128;

    const int c0 = tid * 2;
    const int lr0 = c0 >> 2,        lc0 = (c0 & 3) << 3;
    const int lr1 = (c0 + 1) >> 2,  lc1 = ((c0 + 1) & 3) << 3;

    float acc[4][4][4];
#pragma unroll
    for (int i = 0; i < 4; i++)
#pragma unroll
        for (int j = 0; j < 4; j++)
#pragma unroll
            for (int r = 0; r < 4; r++) acc[i][j][r] = 0.f;

    auto load_stage1 = [&](int kt, int buf) {
        uint32_t s = sb + buf * STAGE_BYTES;
        uint32_t d0 = (uint32_t)(lr0 * PADK + lc0) * 2;
        uint32_t d1 = (uint32_t)(lr1 * PADK + lc1) * 2;
        size_t gA0 = (size_t)(row0 + lr0) * 128 + kt + lc0;
        size_t gA1 = (size_t)(row0 + lr1) * 128 + kt + lc1;
        size_t gW0 = (size_t)lr0 * 128 + kt + lc0;
        size_t gW1 = (size_t)lr1 * 128 + kt + lc1;
        cp_async16(s + OFF_AH + d0, Ah + gA0);
        cp_async16(s + OFF_AH + d1, Ah + gA1);
        cp_async16(s + OFF_AL + d0, Al + gA0);
        cp_async16(s + OFF_AL + d1, Al + gA1);
        cp_async16(s + OFF_WH + d0, W1h + gW0);
        cp_async16(s + OFF_WH + d1, W1h + gW1);
        cp_async16(s + OFF_WL + d0, W1l + gW0);
        cp_async16(s + OFF_WL + d1, W1l + gW1);
    };

    load_stage1(0, 0);
    cp_commit();
    for (int s = 0; s < 4; s++) {
        cp_wait0();
        __syncthreads();
        if (s + 1 < 4) { load_stage1((s + 1) * 32, (s + 1) & 1); cp_commit(); }
        const uint32_t base = sb + (s & 1) * STAGE_BYTES;
#pragma unroll
        for (int ks = 0; ks < 2; ks++) {
            const int k0 = ks * 16;
            uint32_t fah[4][4], fal[4][4], fbh[4][2], fbl[4][2];
            load_a_frags(base + OFF_AH, base + OFF_AL, wm, lane, k0, fah, fal);
            load_b_frags(base + OFF_WH, base + OFF_WL, wn, lane, k0, fbh, fbl);
            mma_block(acc, fah, fal, fbh, fbl);
        }
    }
    __syncthreads();

#pragma unroll
    for (int mi = 0; mi < 4; mi++) {
#pragma unroll
        for (int ni = 0; ni < 4; ni++) {
            int r  = wm + mi * 16 + (lane >> 2);
            int c  = wn + ni * 8 + ((lane & 3) << 1);
            int kc = c >> 5, cc = c & 31;
            uint32_t hbase = sb + (uint32_t)kc * (2 * MAT_BYTES);
            float b0 = b1[c], bb1 = b1[c + 1];
            float v00 = fmaxf(acc[mi][ni][0] + b0, 0.f), v01 = fmaxf(acc[mi][ni][1] + bb1, 0.f);
            float v10 = fmaxf(acc[mi][ni][2] + b0, 0.f), v11 = fmaxf(acc[mi][ni][3] + bb1, 0.f);
            uint32_t hi, lo;
            split2(v00, v01, hi, lo);
            asm volatile("st.shared.b32 [%0], %1;" :: "r"(hbase + (uint32_t)(r * PADK + cc) * 2), "r"(hi) : "memory");
            asm volatile("st.shared.b32 [%0], %1;" :: "r"(hbase + MAT_BYTES + (uint32_t)(r * PADK + cc) * 2), "r"(lo) : "memory");
            split2(v10, v11, hi, lo);
            asm volatile("st.shared.b32 [%0], %1;" :: "r"(hbase + (uint32_t)((r + 8) * PADK + cc) * 2), "r"(hi) : "memory");
            asm volatile("st.shared.b32 [%0], %1;" :: "r"(hbase + MAT_BYTES + (uint32_t)((r + 8) * PADK + cc) * 2), "r"(lo) : "memory");
        }
    }

#pragma unroll
    for (int i = 0; i < 4; i++)
#pragma unroll
        for (int j = 0; j < 4; j++)
#pragma unroll
            for (int r = 0; r < 4; r++) acc[i][j][r] = 0.f;

    const uint32_t w2base = sb + 2 * STAGE_BYTES;
    for (int kc = 0; kc < 4; kc++) {
        {
            uint32_t d0 = (uint32_t)(lr0 * PADK + lc0) * 2;
            uint32_t d1 = (uint32_t)(lr1 * PADK + lc1) * 2;
            size_t gW0 = (size_t)lr0 * 128 + kc * 32 + lc0;
            size_t gW1 = (size_t)lr1 * 128 + kc * 32 + lc1;
            cp_async16(w2base + d0,             W2h + gW0);
            cp_async16(w2base + d1,             W2h + gW1);
            cp_async16(w2base + MAT_BYTES + d0, W2l + gW0);
            cp_async16(w2base + MAT_BYTES + d1, W2l + gW1);
        }
        cp_commit();
        cp_wait0();
        __syncthreads();

        const uint32_t hbase = sb + (uint32_t)kc * (2 * MAT_BYTES);
#pragma unroll
        for (int ks = 0; ks < 2; ks++) {
            const int k0 = ks * 16;
            uint32_t fah[4][4], fal[4][4], fbh[4][2], fbl[4][2];
            load_a_frags(hbase, hbase + MAT_BYTES, wm, lane, k0, fah, fal);
            load_b_frags(w2base, w2base + MAT_BYTES, wn, lane, k0, fbh, fbl);
            mma_block(acc, fah, fal, fbh, fbl);
        }
        __syncthreads();
    }

#pragma unroll
    for (int mi = 0; mi < 4; mi++) {
#pragma unroll
        for (int ni = 0; ni < 4; ni++) {
            int r0 = row0 + wm + mi * 16 + (lane >> 2);
            int c  = wn + ni * 8 + ((lane & 3) << 1);
            float b0 = b2[c], bb1 = b2[c + 1];
            *(float2*)&out[(size_t)r0 * 128 + c] =
                make_float2(acc[mi][ni][0] + b0, acc[mi][ni][1] + bb1);
            *(float2*)&out[(size_t)(r0 + 8) * 128 + c] =
                make_float2(acc[mi][ni][2] + b0, acc[mi][ni][3] + bb1);
        }
    }
}

// ---------------- flash MMA attention, warp-parallel m-tiles ---------------------
// Block = 384 threads / 12 warps; grid (N, B, 2); z = head-group hg.
// Warp w: head hw = w&3 (global hg*4+hw), mt-group grp = w>>2 with balanced key-tile
// counts ({7,3},{6,4},{5,2,1,0} = 12 tiles each). Per 16-key tile: QK (3-term split
// MMA), online softmax (rescale in fp32 accumulators), P repack, PV. S lives in 8
// registers (no spills). Frag maps identical to the verified R11 kernel.
#define ATT_PAD 72
#define ATT_MAT (128 * ATT_PAD * 2)    // 18432
#define ATT_SMEM (6 * ATT_MAT)         // 110592

__global__ __launch_bounds__(384, 2)
void attn_mma()
{
    extern __shared__ __align__(16) char smem[];
    const uint32_t sb = smem_u32(smem);

    const int n  = blockIdx.x;
    const int b  = blockIdx.y;
    const int hg = blockIdx.z;
    const int tid = threadIdx.x, lane = tid & 31, wid = tid >> 5;
    const int hw  = wid & 3;           // head within group
    const int grp = wid >> 2;          // mt-group 0..2
    const int h_global = hg * 4 + hw;

    const size_t rowbase = (size_t)(b * 128) * 256 + n;    // global row of p=0

    // ---- stage Q,K,V head-group slices (64 cols, split bf16) via cp.async ----
    {
        const __nv_bfloat16* srcs[6] = { g_q_hi, g_q_lo, g_k_hi, g_k_lo, g_v_hi, g_v_lo };
#pragma unroll
        for (int m = 0; m < 6; m++) {
            const uint16_t* __restrict__ src = (const uint16_t*)srcs[m] + hg * 64;
            uint32_t dstb = sb + (uint32_t)m * ATT_MAT;
#pragma unroll
            for (int j = 0; j < 3; j++) {
                int id = tid + j * 384;
                if (id < 1024) {
                    int row = id >> 3;
                    int c8  = (id & 7) * 8;
                    cp_async16(dstb + (uint32_t)(row * ATT_PAD + c8) * 2,
                               src + (rowbase + (size_t)row * 256) * 128 + c8);
                }
            }
        }
    }
    cp_commit();
    cp_wait0();
    __syncthreads();

    const uint32_t sqh = sb,                sql = sb + ATT_MAT;
    const uint32_t skh = sb + 2 * ATT_MAT,  skl = sb + 3 * ATT_MAT;
    const uint32_t svh = sb + 4 * ATT_MAT,  svl = sb + 5 * ATT_MAT;
    const uint32_t hoff = (uint32_t)hw * 32;

    const int g  = lane >> 2;
    const int tq = lane & 3;
    const float C = 0.36067376022224085f;    // log2(e) / sqrt(16)

    // packed nibble lists: {7,3}, {6,4}, {5,2,1,0}; 0xF terminates
    const uint32_t mtp = (grp == 0) ? 0xFF37u : (grp == 1) ? 0xFF46u : 0x0125u;

    for (int ii = 0; ii < 4; ii++) {
        const int mt = (int)((mtp >> (ii * 4)) & 0xFu);
        if (mt == 15) break;

        // Q fragments for rows mt*16..mt*16+15
        uint32_t qh[4], ql[4];
        {
            uint32_t off = (uint32_t)((mt * 16 + (lane & 15)) * ATT_PAD) * 2
                           + hoff + (uint32_t)((lane >> 4) << 4);
            ldmatrix_x4(qh, sqh + off);
            ldmatrix_x4(ql, sql + off);
        }

        float o0[4] = {0.f, 0.f, 0.f, 0.f};
        float o1[4] = {0.f, 0.f, 0.f, 0.f};
        float m0 = -1e30f, m1 = -1e30f, sum0 = 0.f, sum1 = 0.f;
        const int p0 = mt * 16 + g, p1 = p0 + 8;

        for (int c = 0; c <= mt; c++) {
            // ---- S tile = Q @ K^T for keys [c*16, c*16+16) ----
            float S0[4] = {0.f, 0.f, 0.f, 0.f};
            float S1[4] = {0.f, 0.f, 0.f, 0.f};
            {
                uint32_t off = (uint32_t)((c * 16 + ((lane >> 4) << 3) + (lane & 7)) * ATT_PAD) * 2
                               + hoff + (uint32_t)(((lane >> 3) & 1) << 4);
                uint32_t t[4], kh0[2], kh1[2], kl0[2], kl1[2];
                ldmatrix_x4(t, skh + off);
                kh0[0] = t[0]; kh0[1] = t[1]; kh1[0] = t[2]; kh1[1] = t[3];
                ldmatrix_x4(t, skl + off);
                kl0[0] = t[0]; kl0[1] = t[1]; kl1[0] = t[2]; kl1[1] = t[3];
                mma_bf16(S0, qh, kh0); mma_bf16(S0, qh, kl0); mma_bf16(S0, ql, kh0);
                mma_bf16(S1, qh, kh1); mma_bf16(S1, qh, kl1); mma_bf16(S1, ql, kh1);
            }

            // ---- causal mask: only the diagonal tile has invalid keys ----
            if (c == mt) {
                int ka = c * 16 + tq * 2;
                if (ka     > p0) S0[0] = -1e30f;
                if (ka + 1 > p0) S0[1] = -1e30f;
                if (ka     > p1) S0[2] = -1e30f;
                if (ka + 1 > p1) S0[3] = -1e30f;
                if (ka + 8 > p0) S1[0] = -1e30f;
                if (ka + 9 > p0) S1[1] = -1e30f;
                if (ka + 8 > p1) S1[2] = -1e30f;
                if (ka + 9 > p1) S1[3] = -1e30f;
            }

            // ---- tile row max (uniform over the 4 tq lanes of each row) ----
            float t0 = fmaxf(fmaxf(S0[0], S0[1]), fmaxf(S1[0], S1[1]));
            float t1 = fmaxf(fmaxf(S0[2], S0[3]), fmaxf(S1[2], S1[3]));
            t0 = fmaxf(t0, __shfl_xor_sync(0xffffffffu, t0, 1));
            t0 = fmaxf(t0, __shfl_xor_sync(0xffffffffu, t0, 2));
            t1 = fmaxf(t1, __shfl_xor_sync(0xffffffffu, t1, 1));
            t1 = fmaxf(t1, __shfl_xor_sync(0xffffffffu, t1, 2));

            // ---- online rescale of running state ----
            float nm0 = fmaxf(m0, t0), nm1 = fmaxf(m1, t1);
            float r0 = ex2f((m0 - nm0) * C), r1 = ex2f((m1 - nm1) * C);
            m0 = nm0; m1 = nm1;
            sum0 *= r0; sum1 *= r1;
            o0[0] *= r0; o0[1] *= r0; o1[0] *= r0; o1[1] *= r0;
            o0[2] *= r1; o0[3] *= r1; o1[2] *= r1; o1[3] *= r1;

            // ---- exp + partial sums ----
            S0[0] = ex2f((S0[0] - m0) * C); S0[1] = ex2f((S0[1] - m0) * C);
            S0[2] = ex2f((S0[2] - m1) * C); S0[3] = ex2f((S0[3] - m1) * C);
            S1[0] = ex2f((S1[0] - m0) * C); S1[1] = ex2f((S1[1] - m0) * C);
            S1[2] = ex2f((S1[2] - m1) * C); S1[3] = ex2f((S1[3] - m1) * C);
            sum0 += S0[0] + S0[1] + S1[0] + S1[1];
            sum1 += S0[2] + S0[3] + S1[2] + S1[3];

            // ---- PV: o += P @ V ----
            uint32_t ph[4], pl[4];
            split2(S0[0], S0[1], ph[0], pl[0]);
            split2(S0[2], S0[3], ph[1], pl[1]);
            split2(S1[0], S1[1], ph[2], pl[2]);
            split2(S1[2], S1[3], ph[3], pl[3]);
            {
                uint32_t off = (uint32_t)((c * 16 + (((lane >> 3) & 1) << 3) + (lane & 7)) * ATT_PAD) * 2
                               + hoff + (uint32_t)((lane >> 4) << 4);
                uint32_t t[4], vh0[2], vh1[2], vl0[2], vl1[2];
                ldmatrix_x4t(t, svh + off);
                vh0[0] = t[0]; vh0[1] = t[1]; vh1[0] = t[2]; vh1[1] = t[3];
                ldmatrix_x4t(t, svl + off);
                vl0[0] = t[0]; vl0[1] = t[1]; vl1[0] = t[2]; vl1[1] = t[3];
                mma_bf16(o0, ph, vh0); mma_bf16(o0, ph, vl0); mma_bf16(o0, pl, vh0);
                mma_bf16(o1, ph, vh1); mma_bf16(o1, ph, vl1); mma_bf16(o1, pl, vh1);
            }
        }

        // ---- reduce denominators over tq lanes, normalize, write split bf16 ----
        sum0 += __shfl_xor_sync(0xffffffffu, sum0, 1);
        sum0 += __shfl_xor_sync(0xffffffffu, sum0, 2);
        sum1 += __shfl_xor_sync(0xffffffffu, sum1, 1);
        sum1 += __shfl_xor_sync(0xffffffffu, sum1, 2);
        const float inv0 = 1.f / sum0, inv1 = 1.f / sum1;

        const size_t r0b = (rowbase + (size_t)p0 * 256) * 128 + h_global * 16 + tq * 2;
        const size_t r1b = (rowbase + (size_t)p1 * 256) * 128 + h_global * 16 + tq * 2;
        uint32_t hi, lo;
        split2(o0[0] * inv0, o0[1] * inv0, hi, lo);
        *(uint32_t*)((uint16_t*)g_att_hi + r0b) = hi;
        *(uint32_t*)((uint16_t*)g_att_lo + r0b) = lo;
        split2(o0[2] * inv1, o0[3] * inv1, hi, lo);
        *(uint32_t*)((uint16_t*)g_att_hi + r1b) = hi;
        *(uint32_t*)((uint16_t*)g_att_lo + r1b) = lo;
        split2(o1[0] * inv0, o1[1] * inv0, hi, lo);
        *(uint32_t*)((uint16_t*)g_att_hi + r0b + 8) = hi;
        *(uint32_t*)((uint16_t*)g_att_lo + r0b + 8) = lo;
        split2(o1[2] * inv1, o1[3] * inv1, hi, lo);
        *(uint32_t*)((uint16_t*)g_att_hi + r1b + 8) = hi;
        *(uint32_t*)((uint16_t*)g_att_lo + r1b + 8) = lo;
    }
}

// ---------------- launch -------------------------------------------------------
extern "C" void kernel_launch(void* const* d_in, const int* in_sizes, int n_in,
                              void* d_out, int out_size)
{
    const float* X   = (const float*)d_in[0];
    const float* STE = (const float*)d_in[1];
    const float* Wq  = (const float*)d_in[2];
    const float* bq  = (const float*)d_in[3];
    const float* Wk  = (const float*)d_in[4];
    const float* bk  = (const float*)d_in[5];
    const float* Wv  = (const float*)d_in[6];
    const float* bv  = (const float*)d_in[7];
    const float* W1  = (const float*)d_in[8];
    const float* b1  = (const float*)d_in[9];
    const float* W2  = (const float*)d_in[10];
    const float* b2  = (const float*)d_in[11];
    float* out = (float*)d_out;

    cudaFuncSetAttribute(qkv_gemm,  cudaFuncAttributeMaxDynamicSharedMemorySize, QKV_SMEM);
    cudaFuncSetAttribute(mlp_fused, cudaFuncAttributeMaxDynamicSharedMemorySize, MLP_SMEM);
    cudaFuncSetAttribute(attn_mma,  cudaFuncAttributeMaxDynamicSharedMemorySize, ATT_SMEM);

    // preprocessing: weight transpose+split, activation concat+split
    convert_w<<<512, 256>>>(Wq, Wk, Wv, W1, W2);
    convert_a<<<32768, 256>>>(X, STE);

    // fused QKV projections (x = weight select -> L2-shared A tiles), split-bf16 out
    qkv_gemm<<<dim3(3, M_ / 128), 256, QKV_SMEM>>>(bq, bk, bv);

    // flash MMA attention: block per (n, b, head-group), 12 warps
    attn_mma<<<dim3(N_, B_, 2), 384, ATT_SMEM>>>();

    // fused output MLP
    mlp_fused<<<M_ / 128, 256, MLP_SMEM>>>(b1, b2, out);
}

// round 15
// speedup vs baseline: 1.6631x; 1.2559x over previous
#include <cuda_runtime.h>
#include <cuda_bf16.h>
#include <cuda_fp16.h>
#include <math.h>
#include <stdint.h>

#define B_   8
#define P_   128
#define N_   256
#define D_   128
#define M_   (B_*P_*N_)        // 262144 rows
#define ROWSTRIDE_ 32768       // N_*D_ elements between consecutive p for fixed (b,n)

// ---------------- scratch (device globals; no allocation allowed) ----------------
__device__ __align__(16) __half g_a[(size_t)M_ * 256];            // fp16 concat(X,STE)
__device__ __align__(16) __nv_bfloat16 g_q_hi[(size_t)M_ * D_];   // attention inputs: split bf16
__device__ __align__(16) __nv_bfloat16 g_q_lo[(size_t)M_ * D_];
__device__ __align__(16) __nv_bfloat16 g_k_hi[(size_t)M_ * D_];
__device__ __align__(16) __nv_bfloat16 g_k_lo[(size_t)M_ * D_];
__device__ __align__(16) __nv_bfloat16 g_v_hi[(size_t)M_ * D_];
__device__ __align__(16) __nv_bfloat16 g_v_lo[(size_t)M_ * D_];
__device__ __align__(16) __half g_att[(size_t)M_ * D_];           // fp16 attention output
// weights transposed to [n][k], fp16-split. layout: Wq(32768) Wk Wv W1(16384) W2
__device__ __align__(16) __half g_wh[131072];
__device__ __align__(16) __half g_wl[131072];

// ---------------- helpers ----------------
__device__ __forceinline__ uint32_t smem_u32(const void* p) {
    uint32_t a;
    asm("{ .reg .u64 t; cvta.to.shared.u64 t, %1; cvt.u32.u64 %0, t; }" : "=r"(a) : "l"(p));
    return a;
}
// bf16 split (attention path)
__device__ __forceinline__ void split_bf16(float x, uint16_t& h, uint16_t& l) {
    __nv_bfloat16 hb = __float2bfloat16(x);
    __nv_bfloat16 lb = __float2bfloat16(x - __bfloat162float(hb));
    h = __bfloat16_as_ushort(hb);
    l = __bfloat16_as_ushort(lb);
}
__device__ __forceinline__ void split2(float a, float b, uint32_t& hi, uint32_t& lo) {
    uint16_t ha, la, hb, lb;
    split_bf16(a, ha, la);
    split_bf16(b, hb, lb);
    hi = (uint32_t)ha | ((uint32_t)hb << 16);
    lo = (uint32_t)la | ((uint32_t)lb << 16);
}
// fp16 helpers (GEMM path)
__device__ __forceinline__ uint32_t packh2(float a, float b) {
    __half2 h = __floats2half2_rn(a, b);
    return *(uint32_t*)&h;
}
__device__ __forceinline__ float ex2f(float x) {
    float y; asm("ex2.approx.f32 %0, %1;" : "=f"(y) : "f"(x)); return y;
}
__device__ __forceinline__ void ldmatrix_x4(uint32_t* r, uint32_t addr) {
    asm volatile("ldmatrix.sync.aligned.m8n8.x4.shared.b16 {%0,%1,%2,%3}, [%4];"
                 : "=r"(r[0]), "=r"(r[1]), "=r"(r[2]), "=r"(r[3]) : "r"(addr));
}
__device__ __forceinline__ void ldmatrix_x4t(uint32_t* r, uint32_t addr) {
    asm volatile("ldmatrix.sync.aligned.m8n8.x4.trans.shared.b16 {%0,%1,%2,%3}, [%4];"
                 : "=r"(r[0]), "=r"(r[1]), "=r"(r[2]), "=r"(r[3]) : "r"(addr));
}
__device__ __forceinline__ void mma_bf16(float* d, const uint32_t* a, const uint32_t* b) {
    asm volatile(
        "mma.sync.aligned.m16n8k16.row.col.f32.bf16.bf16.f32 "
        "{%0,%1,%2,%3}, {%4,%5,%6,%7}, {%8,%9}, {%0,%1,%2,%3};"
        : "+f"(d[0]), "+f"(d[1]), "+f"(d[2]), "+f"(d[3])
        : "r"(a[0]), "r"(a[1]), "r"(a[2]), "r"(a[3]), "r"(b[0]), "r"(b[1]));
}
__device__ __forceinline__ void mma_f16(float* d, const uint32_t* a, const uint32_t* b) {
    asm volatile(
        "mma.sync.aligned.m16n8k16.row.col.f32.f16.f16.f32 "
        "{%0,%1,%2,%3}, {%4,%5,%6,%7}, {%8,%9}, {%0,%1,%2,%3};"
        : "+f"(d[0]), "+f"(d[1]), "+f"(d[2]), "+f"(d[3])
        : "r"(a[0]), "r"(a[1]), "r"(a[2]), "r"(a[3]), "r"(b[0]), "r"(b[1]));
}
__device__ __forceinline__ void cp_async16(uint32_t dst, const void* src) {
    asm volatile("cp.async.cg.shared.global [%0], [%1], 16;" :: "r"(dst), "l"(src));
}
__device__ __forceinline__ void cp_commit() {
    asm volatile("cp.async.commit_group;" ::: "memory");
}
__device__ __forceinline__ void cp_wait0() {
    asm volatile("cp.async.wait_group 0;" ::: "memory");
}

// ---------------- convert weights: W[k][n] fp32 -> transposed fp16 split ----------
__global__ void convert_w(const float* __restrict__ Wq, const float* __restrict__ Wk,
                          const float* __restrict__ Wv, const float* __restrict__ W1,
                          const float* __restrict__ W2)
{
    int id = blockIdx.x * 256 + threadIdx.x;      // < 131072
    const float* src; int K, n, k; size_t dofs;
    if (id < 98304) {
        int wi = id >> 15, rem = id & 32767;
        k = rem >> 7; n = rem & 127; K = 256;
        src = (wi == 0) ? Wq : (wi == 1) ? Wk : Wv;
        dofs = (size_t)wi * 32768;
    } else {
        int r2 = id - 98304;
        int wi = r2 >> 14, rem = r2 & 16383;
        k = rem >> 7; n = rem & 127; K = 128;
        src = wi ? W2 : W1;
        dofs = 98304 + (size_t)wi * 16384;
    }
    float x = src[(size_t)k * 128 + n];
    __half h = __float2half_rn(x);
    __half l = __float2half_rn(x - __half2float(h));
    size_t d = dofs + (size_t)n * K + k;
    ((uint16_t*)g_wh)[d] = __half_as_ushort(h);
    ((uint16_t*)g_wl)[d] = __half_as_ushort(l);
}

// ---------------- convert activations: concat(X,STE) -> fp16 [M x 256] -----------
__global__ void convert_a(const float* __restrict__ X, const float* __restrict__ STE)
{
    size_t id = (size_t)blockIdx.x * 256 + threadIdx.x;   // one per 8 elements
    int row = (int)(id >> 5);
    int c8  = (int)(id & 31) << 3;
    const float* src = (c8 < 128) ? (X + (size_t)row * 128 + c8)
                                  : (STE + (size_t)row * 128 + (c8 - 128));
    float4 v0 = ((const float4*)src)[0];
    float4 v1 = ((const float4*)src)[1];
    uint4 o;
    o.x = packh2(v0.x, v0.y);
    o.y = packh2(v0.z, v0.w);
    o.z = packh2(v1.x, v1.y);
    o.w = packh2(v1.z, v1.w);
    *(uint4*)((uint16_t*)g_a + (size_t)row * 256 + c8) = o;
}

// ---------------- shared GEMM tile constants ------------------------------------
#define PADK 40                       // 80B row stride: 16B-aligned, ldmatrix conflict-free
#define MAT_BYTES (128 * PADK * 2)    // 10240
#define STAGE2 (3 * MAT_BYTES)        // 30720: [A | Wh | Wl]
#define QKV_SMEM (2 * STAGE2)         // 61440
#define MLP_SMEM (2 * STAGE2 + 2 * MAT_BYTES)   // 81920 (H chunks reuse stage; +W2)

__device__ __forceinline__ void load_a1_frags(uint32_t base, int wm, int lane, int k0,
                                              uint32_t fa[4][4]) {
#pragma unroll
    for (int mi = 0; mi < 4; mi++) {
        uint32_t off = (uint32_t)((wm + mi * 16 + (lane & 15)) * PADK
                                  + k0 + ((lane >> 4) << 3)) * 2;
        ldmatrix_x4(fa[mi], base + off);
    }
}
__device__ __forceinline__ void load_b_frags(uint32_t base_h, uint32_t base_l,
                                             int wn, int lane, int k0,
                                             uint32_t fbh[4][2], uint32_t fbl[4][2]) {
#pragma unroll
    for (int njp = 0; njp < 2; njp++) {
        uint32_t off = (uint32_t)((wn + njp * 16 + ((lane >> 4) << 3) + (lane & 7)) * PADK
                                  + k0 + (((lane >> 3) & 1) << 3)) * 2;
        uint32_t t[4];
        ldmatrix_x4(t, base_h + off);
        fbh[2*njp][0] = t[0]; fbh[2*njp][1] = t[1];
        fbh[2*njp+1][0] = t[2]; fbh[2*njp+1][1] = t[3];
        ldmatrix_x4(t, base_l + off);
        fbl[2*njp][0] = t[0]; fbl[2*njp][1] = t[1];
        fbl[2*njp+1][0] = t[2]; fbl[2*njp+1][1] = t[3];
    }
}
__device__ __forceinline__ void mma_block2(float acc[4][4][4],
                                           uint32_t fa[4][4],
                                           uint32_t fbh[4][2], uint32_t fbl[4][2]) {
#pragma unroll
    for (int mi = 0; mi < 4; mi++)
#pragma unroll
        for (int ni = 0; ni < 4; ni++) {
            mma_f16(acc[mi][ni], fa[mi], fbh[ni]);
            mma_f16(acc[mi][ni], fa[mi], fbl[ni]);
        }
}

// ---------------- fused QKV GEMM (fp16 2-term; split-bf16 epilogue) ---------------
__global__ __launch_bounds__(256)
void qkv_gemm(const float* __restrict__ bq, const float* __restrict__ bk,
              const float* __restrict__ bv)
{
    extern __shared__ __align__(16) char smem[];
    const uint32_t sb = smem_u32(smem);

    const int wsel = blockIdx.x;
    const int row0 = blockIdx.y * 128;
    const __half* __restrict__ A  = g_a;
    const __half* __restrict__ Wh = g_wh + wsel * 32768;
    const __half* __restrict__ Wl = g_wl + wsel * 32768;
    const float* __restrict__ bias = (wsel == 0) ? bq : (wsel == 1) ? bk : bv;
    uint16_t* __restrict__ oh = (uint16_t*)((wsel == 0) ? g_q_hi : (wsel == 1) ? g_k_hi : g_v_hi);
    uint16_t* __restrict__ ol = (uint16_t*)((wsel == 0) ? g_q_lo : (wsel == 1) ? g_k_lo : g_v_lo);

    const int tid  = threadIdx.x;
    const int lane = tid & 31;
    const int wid  = tid >> 5;
    const int wm   = (wid & 1) * 64;
    const int wn   = (wid >> 1) * 32;

    float acc[4][4][4];
#pragma unroll
    for (int i = 0; i < 4; i++)
#pragma unroll
        for (int j = 0; j < 4; j++)
#pragma unroll
            for (int r = 0; r < 4; r++) acc[i][j][r] = 0.f;

    const int c0 = tid * 2;
    const int lr0 = c0 >> 2,        lc0 = (c0 & 3) << 3;
    const int lr1 = (c0 + 1) >> 2,  lc1 = ((c0 + 1) & 3) << 3;

    auto load_stage = [&](int kt, int buf) {
        uint32_t s = sb + buf * STAGE2;
        uint32_t d0 = (uint32_t)(lr0 * PADK + lc0) * 2;
        uint32_t d1 = (uint32_t)(lr1 * PADK + lc1) * 2;
        size_t gA0 = (size_t)(row0 + lr0) * 256 + kt + lc0;
        size_t gA1 = (size_t)(row0 + lr1) * 256 + kt + lc1;
        size_t gW0 = (size_t)lr0 * 256 + kt + lc0;
        size_t gW1 = (size_t)lr1 * 256 + kt + lc1;
        cp_async16(s + d0,                 A + gA0);
        cp_async16(s + d1,                 A + gA1);
        cp_async16(s + MAT_BYTES + d0,     Wh + gW0);
        cp_async16(s + MAT_BYTES + d1,     Wh + gW1);
        cp_async16(s + 2 * MAT_BYTES + d0, Wl + gW0);
        cp_async16(s + 2 * MAT_BYTES + d1, Wl + gW1);
    };

    const int NS = 8;
    load_stage(0, 0);
    cp_commit();

    for (int s = 0; s < NS; s++) {
        cp_wait0();
        __syncthreads();
        if (s + 1 < NS) { load_stage((s + 1) * 32, (s + 1) & 1); cp_commit(); }

        const uint32_t base = sb + (s & 1) * STAGE2;
#pragma unroll
        for (int ks = 0; ks < 2; ks++) {
            const int k0 = ks * 16;
            uint32_t fa[4][4], fbh[4][2], fbl[4][2];
            load_a1_frags(base, wm, lane, k0, fa);
            load_b_frags(base + MAT_BYTES, base + 2 * MAT_BYTES, wn, lane, k0, fbh, fbl);
            mma_block2(acc, fa, fbh, fbl);
        }
    }

#pragma unroll
    for (int mi = 0; mi < 4; mi++) {
#pragma unroll
        for (int ni = 0; ni < 4; ni++) {
            int r0 = row0 + wm + mi * 16 + (lane >> 2);
            int c  = wn + ni * 8 + ((lane & 3) << 1);
            float b0 = bias[c], b1 = bias[c + 1];
            float v00 = fmaxf(acc[mi][ni][0] + b0, 0.f), v01 = fmaxf(acc[mi][ni][1] + b1, 0.f);
            float v10 = fmaxf(acc[mi][ni][2] + b0, 0.f), v11 = fmaxf(acc[mi][ni][3] + b1, 0.f);
            uint32_t hi, lo;
            split2(v00, v01, hi, lo);
            *(uint32_t*)(oh + (size_t)r0 * 128 + c) = hi;
            *(uint32_t*)(ol + (size_t)r0 * 128 + c) = lo;
            split2(v10, v11, hi, lo);
            *(uint32_t*)(oh + (size_t)(r0 + 8) * 128 + c) = hi;
            *(uint32_t*)(ol + (size_t)(r0 + 8) * 128 + c) = lo;
        }
    }
}

// ---------------- fused MLP (fp16 2-term) ----------------------------------------
__global__ __launch_bounds__(256)
void mlp_fused(const float* __restrict__ b1, const float* __restrict__ b2,
               float* __restrict__ out)
{
    extern __shared__ __align__(16) char smem[];
    const uint32_t sb = smem_u32(smem);

    const __half* __restrict__ Ah  = g_att;
    const __half* __restrict__ W1h = g_wh + 98304;
    const __half* __restrict__ W1l = g_wl + 98304;
    const __half* __restrict__ W2h = g_wh + 114688;
    const __half* __restrict__ W2l = g_wl + 114688;

    const int tid  = threadIdx.x;
    const int lane = tid & 31;
    const int wid  = tid >> 5;
    const int wm   = (wid & 1) * 64;
    const int wn   = (wid >> 1) * 32;
    const int row0 = blockIdx.x * 128;

    const int c0 = tid * 2;
    const int lr0 = c0 >> 2,        lc0 = (c0 & 3) << 3;
    const int lr1 = (c0 + 1) >> 2,  lc1 = ((c0 + 1) & 3) << 3;

    float acc[4][4][4];
#pragma unroll
    for (int i = 0; i < 4; i++)
#pragma unroll
        for (int j = 0; j < 4; j++)
#pragma unroll
            for (int r = 0; r < 4; r++) acc[i][j][r] = 0.f;

    // ---- phase 1: h = relu(att @ W1 + b1) ----
    auto load_stage1 = [&](int kt, int buf) {
        uint32_t s = sb + buf * STAGE2;
        uint32_t d0 = (uint32_t)(lr0 * PADK + lc0) * 2;
        uint32_t d1 = (uint32_t)(lr1 * PADK + lc1) * 2;
        size_t gA0 = (size_t)(row0 + lr0) * 128 + kt + lc0;
        size_t gA1 = (size_t)(row0 + lr1) * 128 + kt + lc1;
        size_t gW0 = (size_t)lr0 * 128 + kt + lc0;
        size_t gW1 = (size_t)lr1 * 128 + kt + lc1;
        cp_async16(s + d0,                 Ah + gA0);
        cp_async16(s + d1,                 Ah + gA1);
        cp_async16(s + MAT_BYTES + d0,     W1h + gW0);
        cp_async16(s + MAT_BYTES + d1,     W1h + gW1);
        cp_async16(s + 2 * MAT_BYTES + d0, W1l + gW0);
        cp_async16(s + 2 * MAT_BYTES + d1, W1l + gW1);
    };

    load_stage1(0, 0);
    cp_commit();
    for (int s = 0; s < 4; s++) {
        cp_wait0();
        __syncthreads();
        if (s + 1 < 4) { load_stage1((s + 1) * 32, (s + 1) & 1); cp_commit(); }
        const uint32_t base = sb + (s & 1) * STAGE2;
#pragma unroll
        for (int ks = 0; ks < 2; ks++) {
            const int k0 = ks * 16;
            uint32_t fa[4][4], fbh[4][2], fbl[4][2];
            load_a1_frags(base, wm, lane, k0, fa);
            load_b_frags(base + MAT_BYTES, base + 2 * MAT_BYTES, wn, lane, k0, fbh, fbl);
            mma_block2(acc, fa, fbh, fbl);
        }
    }
    __syncthreads();   // all warps done reading stage buffers before H overwrites them

    // write h (relu + b1, fp16) into SMEM H chunks: chunk kc at sb + kc*MAT_BYTES
#pragma unroll
    for (int mi = 0; mi < 4; mi++) {
#pragma unroll
        for (int ni = 0; ni < 4; ni++) {
            int r  = wm + mi * 16 + (lane >> 2);
            int c  = wn + ni * 8 + ((lane & 3) << 1);
            int kc = c >> 5, cc = c & 31;
            uint32_t hbase = sb + (uint32_t)kc * MAT_BYTES;
            float b0 = b1[c], bb1 = b1[c + 1];
            float v00 = fmaxf(acc[mi][ni][0] + b0, 0.f), v01 = fmaxf(acc[mi][ni][1] + bb1, 0.f);
            float v10 = fmaxf(acc[mi][ni][2] + b0, 0.f), v11 = fmaxf(acc[mi][ni][3] + bb1, 0.f);
            asm volatile("st.shared.b32 [%0], %1;"
                         :: "r"(hbase + (uint32_t)(r * PADK + cc) * 2), "r"(packh2(v00, v01)) : "memory");
            asm volatile("st.shared.b32 [%0], %1;"
                         :: "r"(hbase + (uint32_t)((r + 8) * PADK + cc) * 2), "r"(packh2(v10, v11)) : "memory");
        }
    }

    // ---- phase 2: out = h @ W2 + b2 ----
#pragma unroll
    for (int i = 0; i < 4; i++)
#pragma unroll
        for (int j = 0; j < 4; j++)
#pragma unroll
            for (int r = 0; r < 4; r++) acc[i][j][r] = 0.f;

    const uint32_t w2base = sb + 2 * STAGE2;   // [W2h | W2l]
    for (int kc = 0; kc < 4; kc++) {
        {
            uint32_t d0 = (uint32_t)(lr0 * PADK + lc0) * 2;
            uint32_t d1 = (uint32_t)(lr1 * PADK + lc1) * 2;
            size_t gW0 = (size_t)lr0 * 128 + kc * 32 + lc0;
            size_t gW1 = (size_t)lr1 * 128 + kc * 32 + lc1;
            cp_async16(w2base + d0,             W2h + gW0);
            cp_async16(w2base + d1,             W2h + gW1);
            cp_async16(w2base + MAT_BYTES + d0, W2l + gW0);
            cp_async16(w2base + MAT_BYTES + d1, W2l + gW1);
        }
        cp_commit();
        cp_wait0();
        __syncthreads();   // W2 chunk ready; (kc=0) also orders H writes before reads

        const uint32_t hbase = sb + (uint32_t)kc * MAT_BYTES;
#pragma unroll
        for (int ks = 0; ks < 2; ks++) {
            const int k0 = ks * 16;
            uint32_t fa[4][4], fbh[4][2], fbl[4][2];
            load_a1_frags(hbase, wm, lane, k0, fa);
            load_b_frags(w2base, w2base + MAT_BYTES, wn, lane, k0, fbh, fbl);
            mma_block2(acc, fa, fbh, fbl);
        }
        __syncthreads();   // done reading W2 buffer before next chunk overwrites
    }

#pragma unroll
    for (int mi = 0; mi < 4; mi++) {
#pragma unroll
        for (int ni = 0; ni < 4; ni++) {
            int r0 = row0 + wm + mi * 16 + (lane >> 2);
            int c  = wn + ni * 8 + ((lane & 3) << 1);
            float b0 = b2[c], bb1 = b2[c + 1];
            *(float2*)&out[(size_t)r0 * 128 + c] =
                make_float2(acc[mi][ni][0] + b0, acc[mi][ni][1] + bb1);
            *(float2*)&out[(size_t)(r0 + 8) * 128 + c] =
                make_float2(acc[mi][ni][2] + b0, acc[mi][ni][3] + bb1);
        }
    }
}

// ---------------- flash MMA attention (unchanged math; fp16 output) --------------
#define ATT_PAD 72
#define ATT_MAT (128 * ATT_PAD * 2)    // 18432
#define ATT_SMEM (6 * ATT_MAT)         // 110592

__global__ __launch_bounds__(384, 2)
void attn_mma()
{
    extern __shared__ __align__(16) char smem[];
    const uint32_t sb = smem_u32(smem);

    const int n  = blockIdx.x;
    const int b  = blockIdx.y;
    const int hg = blockIdx.z;
    const int tid = threadIdx.x, lane = tid & 31, wid = tid >> 5;
    const int hw  = wid & 3;
    const int grp = wid >> 2;
    const int h_global = hg * 4 + hw;

    const size_t rowbase = (size_t)(b * 128) * 256 + n;

    // ---- stage Q,K,V head-group slices (64 cols, split bf16) via cp.async ----
    {
        const __nv_bfloat16* srcs[6] = { g_q_hi, g_q_lo, g_k_hi, g_k_lo, g_v_hi, g_v_lo };
#pragma unroll
        for (int m = 0; m < 6; m++) {
            const uint16_t* __restrict__ src = (const uint16_t*)srcs[m] + hg * 64;
            uint32_t dstb = sb + (uint32_t)m * ATT_MAT;
#pragma unroll
            for (int j = 0; j < 3; j++) {
                int id = tid + j * 384;
                if (id < 1024) {
                    int row = id >> 3;
                    int c8  = (id & 7) * 8;
                    cp_async16(dstb + (uint32_t)(row * ATT_PAD + c8) * 2,
                               src + (rowbase + (size_t)row * 256) * 128 + c8);
                }
            }
        }
    }
    cp_commit();
    cp_wait0();
    __syncthreads();

    const uint32_t sqh = sb,                sql = sb + ATT_MAT;
    const uint32_t skh = sb + 2 * ATT_MAT,  skl = sb + 3 * ATT_MAT;
    const uint32_t svh = sb + 4 * ATT_MAT,  svl = sb + 5 * ATT_MAT;
    const uint32_t hoff = (uint32_t)hw * 32;

    const int g  = lane >> 2;
    const int tq = lane & 3;
    const float C = 0.36067376022224085f;    // log2(e) / sqrt(16)

    const uint32_t mtp = (grp == 0) ? 0xFF37u : (grp == 1) ? 0xFF46u : 0x0125u;

    for (int ii = 0; ii < 4; ii++) {
        const int mt = (int)((mtp >> (ii * 4)) & 0xFu);
        if (mt == 15) break;

        uint32_t qh[4], ql[4];
        {
            uint32_t off = (uint32_t)((mt * 16 + (lane & 15)) * ATT_PAD) * 2
                           + hoff + (uint32_t)((lane >> 4) << 4);
            ldmatrix_x4(qh, sqh + off);
            ldmatrix_x4(ql, sql + off);
        }

        float o0[4] = {0.f, 0.f, 0.f, 0.f};
        float o1[4] = {0.f, 0.f, 0.f, 0.f};
        float m0 = -1e30f, m1 = -1e30f, sum0 = 0.f, sum1 = 0.f;
        const int p0 = mt * 16 + g, p1 = p0 + 8;

        for (int c = 0; c <= mt; c++) {
            float S0[4] = {0.f, 0.f, 0.f, 0.f};
            float S1[4] = {0.f, 0.f, 0.f, 0.f};
            {
                uint32_t off = (uint32_t)((c * 16 + ((lane >> 4) << 3) + (lane & 7)) * ATT_PAD) * 2
                               + hoff + (uint32_t)(((lane >> 3) & 1) << 4);
                uint32_t t[4], kh0[2], kh1[2], kl0[2], kl1[2];
                ldmatrix_x4(t, skh + off);
                kh0[0] = t[0]; kh0[1] = t[1]; kh1[0] = t[2]; kh1[1] = t[3];
                ldmatrix_x4(t, skl + off);
                kl0[0] = t[0]; kl0[1] = t[1]; kl1[0] = t[2]; kl1[1] = t[3];
                mma_bf16(S0, qh, kh0); mma_bf16(S0, qh, kl0); mma_bf16(S0, ql, kh0);
                mma_bf16(S1, qh, kh1); mma_bf16(S1, qh, kl1); mma_bf16(S1, ql, kh1);
            }

            if (c == mt) {
                int ka = c * 16 + tq * 2;
                if (ka     > p0) S0[0] = -1e30f;
                if (ka + 1 > p0) S0[1] = -1e30f;
                if (ka     > p1) S0[2] = -1e30f;
                if (ka + 1 > p1) S0[3] = -1e30f;
                if (ka + 8 > p0) S1[0] = -1e30f;
                if (ka + 9 > p0) S1[1] = -1e30f;
                if (ka + 8 > p1) S1[2] = -1e30f;
                if (ka + 9 > p1) S1[3] = -1e30f;
            }

            float t0 = fmaxf(fmaxf(S0[0], S0[1]), fmaxf(S1[0], S1[1]));
            float t1 = fmaxf(fmaxf(S0[2], S0[3]), fmaxf(S1[2], S1[3]));
            t0 = fmaxf(t0, __shfl_xor_sync(0xffffffffu, t0, 1));
            t0 = fmaxf(t0, __shfl_xor_sync(0xffffffffu, t0, 2));
            t1 = fmaxf(t1, __shfl_xor_sync(0xffffffffu, t1, 1));
            t1 = fmaxf(t1, __shfl_xor_sync(0xffffffffu, t1, 2));

            float nm0 = fmaxf(m0, t0), nm1 = fmaxf(m1, t1);
            float r0 = ex2f((m0 - nm0) * C), r1 = ex2f((m1 - nm1) * C);
            m0 = nm0; m1 = nm1;
            sum0 *= r0; sum1 *= r1;
            o0[0] *= r0; o0[1] *= r0; o1[0] *= r0; o1[1] *= r0;
            o0[2] *= r1; o0[3] *= r1; o1[2] *= r1; o1[3] *= r1;

            S0[0] = ex2f((S0[0] - m0) * C); S0[1] = ex2f((S0[1] - m0) * C);
            S0[2] = ex2f((S0[2] - m1) * C); S0[3] = ex2f((S0[3] - m1) * C);
            S1[0] = ex2f((S1[0] - m0) * C); S1[1] = ex2f((S1[1] - m0) * C);
            S1[2] = ex2f((S1[2] - m1) * C); S1[3] = ex2f((S1[3] - m1) * C);
            sum0 += S0[0] + S0[1] + S1[0] + S1[1];
            sum1 += S0[2] + S0[3] + S1[2] + S1[3];

            uint32_t ph[4], pl[4];
            split2(S0[0], S0[1], ph[0], pl[0]);
            split2(S0[2], S0[3], ph[1], pl[1]);
            split2(S1[0], S1[1], ph[2], pl[2]);
            split2(S1[2], S1[3], ph[3], pl[3]);
            {
                uint32_t off = (uint32_t)((c * 16 + (((lane >> 3) & 1) << 3) + (lane & 7)) * ATT_PAD) * 2
                               + hoff + (uint32_t)((lane >> 4) << 4);
                uint32_t t[4], vh0[2], vh1[2], vl0[2], vl1[2];
                ldmatrix_x4t(t, svh + off);
                vh0[0] = t[0]; vh0[1] = t[1]; vh1[0] = t[2]; vh1[1] = t[3];
                ldmatrix_x4t(t, svl + off);
                vl0[0] = t[0]; vl0[1] = t[1]; vl1[0] = t[2]; vl1[1] = t[3];
                mma_bf16(o0, ph, vh0); mma_bf16(o0, ph, vl0); mma_bf16(o0, pl, vh0);
                mma_bf16(o1, ph, vh1); mma_bf16(o1, ph, vl1); mma_bf16(o1, pl, vh1);
            }
        }

        sum0 += __shfl_xor_sync(0xffffffffu, sum0, 1);
        sum0 += __shfl_xor_sync(0xffffffffu, sum0, 2);
        sum1 += __shfl_xor_sync(0xffffffffu, sum1, 1);
        sum1 += __shfl_xor_sync(0xffffffffu, sum1, 2);
        const float inv0 = 1.f / sum0, inv1 = 1.f / sum1;

        const size_t r0b = (rowbase + (size_t)p0 * 256) * 128 + h_global * 16 + tq * 2;
        const size_t r1b = (rowbase + (size_t)p1 * 256) * 128 + h_global * 16 + tq * 2;
        *(uint32_t*)((uint16_t*)g_att + r0b)     = packh2(o0[0] * inv0, o0[1] * inv0);
        *(uint32_t*)((uint16_t*)g_att + r1b)     = packh2(o0[2] * inv1, o0[3] * inv1);
        *(uint32_t*)((uint16_t*)g_att + r0b + 8) = packh2(o1[0] * inv0, o1[1] * inv0);
        *(uint32_t*)((uint16_t*)g_att + r1b + 8) = packh2(o1[2] * inv1, o1[3] * inv1);
    }
}

// ---------------- launch -------------------------------------------------------
extern "C" void kernel_launch(void* const* d_in, const int* in_sizes, int n_in,
                              void* d_out, int out_size)
{
    const float* X   = (const float*)d_in[0];
    const float* STE = (const float*)d_in[1];
    const float* Wq  = (const float*)d_in[2];
    const float* bq  = (const float*)d_in[3];
    const float* Wk  = (const float*)d_in[4];
    const float* bk  = (const float*)d_in[5];
    const float* Wv  = (const float*)d_in[6];
    const float* bv  = (const float*)d_in[7];
    const float* W1  = (const float*)d_in[8];
    const float* b1  = (const float*)d_in[9];
    const float* W2  = (const float*)d_in[10];
    const float* b2  = (const float*)d_in[11];
    float* out = (float*)d_out;

    cudaFuncSetAttribute(qkv_gemm,  cudaFuncAttributeMaxDynamicSharedMemorySize, QKV_SMEM);
    cudaFuncSetAttribute(mlp_fused, cudaFuncAttributeMaxDynamicSharedMemorySize, MLP_SMEM);
    cudaFuncSetAttribute(attn_mma,  cudaFuncAttributeMaxDynamicSharedMemorySize, ATT_SMEM);

    // preprocessing: weight transpose+fp16 split, activation concat+fp16
    convert_w<<<512, 256>>>(Wq, Wk, Wv, W1, W2);
    convert_a<<<32768, 256>>>(X, STE);

    // fused QKV projections (fp16 2-term; x = weight select -> L2-shared A tiles)
    qkv_gemm<<<dim3(3, M_ / 128), 256, QKV_SMEM>>>(bq, bk, bv);

    // flash MMA attention: block per (n, b, head-group), 12 warps
    attn_mma<<<dim3(N_, B_, 2), 384, ATT_SMEM>>>();

    // fused output MLP (fp16 2-term)
    mlp_fused<<<M_ / 128, 256, MLP_SMEM>>>(b1, b2, out);
}

// round 16
// speedup vs baseline: 2.0750x; 1.2476x over previous
#include <cuda_runtime.h>
#include <cuda_bf16.h>
#include <cuda_fp16.h>
#include <math.h>
#include <stdint.h>

#define B_   8
#define P_   128
#define N_   256
#define D_   128
#define M_   (B_*P_*N_)        // 262144 rows
#define ROWSTRIDE_ 32768       // N_*D_ elements between consecutive p for fixed (b,n)

// ---------------- scratch (device globals; no allocation allowed) ----------------
__device__ __align__(16) __half g_a[(size_t)M_ * 256];            // fp16 concat(X,STE)
__device__ __align__(16) __nv_bfloat16 g_q_hi[(size_t)M_ * D_];   // attention inputs: split bf16
__device__ __align__(16) __nv_bfloat16 g_q_lo[(size_t)M_ * D_];
__device__ __align__(16) __nv_bfloat16 g_k_hi[(size_t)M_ * D_];
__device__ __align__(16) __nv_bfloat16 g_k_lo[(size_t)M_ * D_];
__device__ __align__(16) __nv_bfloat16 g_v_hi[(size_t)M_ * D_];
__device__ __align__(16) __nv_bfloat16 g_v_lo[(size_t)M_ * D_];
__device__ __align__(16) __half g_att[(size_t)M_ * D_];           // fp16 attention output
// weights transposed to [n][k], fp16. layout: Wq(32768) Wk Wv W1(16384) W2
__device__ __align__(16) __half g_w[131072];

// ---------------- helpers ----------------
__device__ __forceinline__ uint32_t smem_u32(const void* p) {
    uint32_t a;
    asm("{ .reg .u64 t; cvta.to.shared.u64 t, %1; cvt.u32.u64 %0, t; }" : "=r"(a) : "l"(p));
    return a;
}
// bf16 split (attention path)
__device__ __forceinline__ void split_bf16(float x, uint16_t& h, uint16_t& l) {
    __nv_bfloat16 hb = __float2bfloat16(x);
    __nv_bfloat16 lb = __float2bfloat16(x - __bfloat162float(hb));
    h = __bfloat16_as_ushort(hb);
    l = __bfloat16_as_ushort(lb);
}
__device__ __forceinline__ void split2(float a, float b, uint32_t& hi, uint32_t& lo) {
    uint16_t ha, la, hb, lb;
    split_bf16(a, ha, la);
    split_bf16(b, hb, lb);
    hi = (uint32_t)ha | ((uint32_t)hb << 16);
    lo = (uint32_t)la | ((uint32_t)lb << 16);
}
// fp16 helpers (GEMM path)
__device__ __forceinline__ uint32_t packh2(float a, float b) {
    __half2 h = __floats2half2_rn(a, b);
    return *(uint32_t*)&h;
}
__device__ __forceinline__ float ex2f(float x) {
    float y; asm("ex2.approx.f32 %0, %1;" : "=f"(y) : "f"(x)); return y;
}
__device__ __forceinline__ void ldmatrix_x4(uint32_t* r, uint32_t addr) {
    asm volatile("ldmatrix.sync.aligned.m8n8.x4.shared.b16 {%0,%1,%2,%3}, [%4];"
                 : "=r"(r[0]), "=r"(r[1]), "=r"(r[2]), "=r"(r[3]) : "r"(addr));
}
__device__ __forceinline__ void ldmatrix_x4t(uint32_t* r, uint32_t addr) {
    asm volatile("ldmatrix.sync.aligned.m8n8.x4.trans.shared.b16 {%0,%1,%2,%3}, [%4];"
                 : "=r"(r[0]), "=r"(r[1]), "=r"(r[2]), "=r"(r[3]) : "r"(addr));
}
__device__ __forceinline__ void mma_bf16(float* d, const uint32_t* a, const uint32_t* b) {
    asm volatile(
        "mma.sync.aligned.m16n8k16.row.col.f32.bf16.bf16.f32 "
        "{%0,%1,%2,%3}, {%4,%5,%6,%7}, {%8,%9}, {%0,%1,%2,%3};"
        : "+f"(d[0]), "+f"(d[1]), "+f"(d[2]), "+f"(d[3])
        : "r"(a[0]), "r"(a[1]), "r"(a[2]), "r"(a[3]), "r"(b[0]), "r"(b[1]));
}
__device__ __forceinline__ void mma_f16(float* d, const uint32_t* a, const uint32_t* b) {
    asm volatile(
        "mma.sync.aligned.m16n8k16.row.col.f32.f16.f16.f32 "
        "{%0,%1,%2,%3}, {%4,%5,%6,%7}, {%8,%9}, {%0,%1,%2,%3};"
        : "+f"(d[0]), "+f"(d[1]), "+f"(d[2]), "+f"(d[3])
        : "r"(a[0]), "r"(a[1]), "r"(a[2]), "r"(a[3]), "r"(b[0]), "r"(b[1]));
}
__device__ __forceinline__ void cp_async16(uint32_t dst, const void* src) {
    asm volatile("cp.async.cg.shared.global [%0], [%1], 16;" :: "r"(dst), "l"(src));
}
__device__ __forceinline__ void cp_commit() {
    asm volatile("cp.async.commit_group;" ::: "memory");
}
__device__ __forceinline__ void cp_wait0() {
    asm volatile("cp.async.wait_group 0;" ::: "memory");
}

// ---------------- convert weights: W[k][n] fp32 -> transposed fp16 ---------------
__global__ void convert_w(const float* __restrict__ Wq, const float* __restrict__ Wk,
                          const float* __restrict__ Wv, const float* __restrict__ W1,
                          const float* __restrict__ W2)
{
    int id = blockIdx.x * 256 + threadIdx.x;      // < 131072
    const float* src; int K, n, k; size_t dofs;
    if (id < 98304) {
        int wi = id >> 15, rem = id & 32767;
        k = rem >> 7; n = rem & 127; K = 256;
        src = (wi == 0) ? Wq : (wi == 1) ? Wk : Wv;
        dofs = (size_t)wi * 32768;
    } else {
        int r2 = id - 98304;
        int wi = r2 >> 14, rem = r2 & 16383;
        k = rem >> 7; n = rem & 127; K = 128;
        src = wi ? W2 : W1;
        dofs = 98304 + (size_t)wi * 16384;
    }
    float x = src[(size_t)k * 128 + n];
    ((uint16_t*)g_w)[dofs + (size_t)n * K + k] = __half_as_ushort(__float2half_rn(x));
}

// ---------------- convert activations: concat(X,STE) -> fp16 [M x 256] -----------
__global__ void convert_a(const float* __restrict__ X, const float* __restrict__ STE)
{
    size_t id = (size_t)blockIdx.x * 256 + threadIdx.x;   // one per 8 elements
    int row = (int)(id >> 5);
    int c8  = (int)(id & 31) << 3;
    const float* src = (c8 < 128) ? (X + (size_t)row * 128 + c8)
                                  : (STE + (size_t)row * 128 + (c8 - 128));
    float4 v0 = ((const float4*)src)[0];
    float4 v1 = ((const float4*)src)[1];
    uint4 o;
    o.x = packh2(v0.x, v0.y);
    o.y = packh2(v0.z, v0.w);
    o.z = packh2(v1.x, v1.y);
    o.w = packh2(v1.z, v1.w);
    *(uint4*)((uint16_t*)g_a + (size_t)row * 256 + c8) = o;
}

// ---------------- shared GEMM tile constants ------------------------------------
#define PADK 40                       // 80B row stride: 16B-aligned, ldmatrix conflict-free
#define MAT_BYTES (128 * PADK * 2)    // 10240
#define STAGE1 (2 * MAT_BYTES)        // 20480: [A | W]
#define QKV_SMEM (2 * STAGE1)         // 40960
#define MLP_SMEM (2 * STAGE1 + MAT_BYTES)   // 51200 (H chunks reuse stage; +W2)

__device__ __forceinline__ void load_a1_frags(uint32_t base, int wm, int lane, int k0,
                                              uint32_t fa[4][4]) {
#pragma unroll
    for (int mi = 0; mi < 4; mi++) {
        uint32_t off = (uint32_t)((wm + mi * 16 + (lane & 15)) * PADK
                                  + k0 + ((lane >> 4) << 3)) * 2;
        ldmatrix_x4(fa[mi], base + off);
    }
}
__device__ __forceinline__ void load_b1_frags(uint32_t base, int wn, int lane, int k0,
                                              uint32_t fb[4][2]) {
#pragma unroll
    for (int njp = 0; njp < 2; njp++) {
        uint32_t off = (uint32_t)((wn + njp * 16 + ((lane >> 4) << 3) + (lane & 7)) * PADK
                                  + k0 + (((lane >> 3) & 1) << 3)) * 2;
        uint32_t t[4];
        ldmatrix_x4(t, base + off);
        fb[2*njp][0] = t[0]; fb[2*njp][1] = t[1];
        fb[2*njp+1][0] = t[2]; fb[2*njp+1][1] = t[3];
    }
}
__device__ __forceinline__ void mma_block1(float acc[4][4][4],
                                           uint32_t fa[4][4], uint32_t fb[4][2]) {
#pragma unroll
    for (int mi = 0; mi < 4; mi++)
#pragma unroll
        for (int ni = 0; ni < 4; ni++)
            mma_f16(acc[mi][ni], fa[mi], fb[ni]);
}

// ---------------- fused QKV GEMM (fp16 single; split-bf16 epilogue) ---------------
__global__ __launch_bounds__(256)
void qkv_gemm(const float* __restrict__ bq, const float* __restrict__ bk,
              const float* __restrict__ bv)
{
    extern __shared__ __align__(16) char smem[];
    const uint32_t sb = smem_u32(smem);

    const int wsel = blockIdx.x;
    const int row0 = blockIdx.y * 128;
    const __half* __restrict__ A = g_a;
    const __half* __restrict__ W = g_w + wsel * 32768;
    const float* __restrict__ bias = (wsel == 0) ? bq : (wsel == 1) ? bk : bv;
    uint16_t* __restrict__ oh = (uint16_t*)((wsel == 0) ? g_q_hi : (wsel == 1) ? g_k_hi : g_v_hi);
    uint16_t* __restrict__ ol = (uint16_t*)((wsel == 0) ? g_q_lo : (wsel == 1) ? g_k_lo : g_v_lo);

    const int tid  = threadIdx.x;
    const int lane = tid & 31;
    const int wid  = tid >> 5;
    const int wm   = (wid & 1) * 64;
    const int wn   = (wid >> 1) * 32;

    float acc[4][4][4];
#pragma unroll
    for (int i = 0; i < 4; i++)
#pragma unroll
        for (int j = 0; j < 4; j++)
#pragma unroll
            for (int r = 0; r < 4; r++) acc[i][j][r] = 0.f;

    const int c0 = tid * 2;
    const int lr0 = c0 >> 2,        lc0 = (c0 & 3) << 3;
    const int lr1 = (c0 + 1) >> 2,  lc1 = ((c0 + 1) & 3) << 3;

    auto load_stage = [&](int kt, int buf) {
        uint32_t s = sb + buf * STAGE1;
        uint32_t d0 = (uint32_t)(lr0 * PADK + lc0) * 2;
        uint32_t d1 = (uint32_t)(lr1 * PADK + lc1) * 2;
        size_t gA0 = (size_t)(row0 + lr0) * 256 + kt + lc0;
        size_t gA1 = (size_t)(row0 + lr1) * 256 + kt + lc1;
        size_t gW0 = (size_t)lr0 * 256 + kt + lc0;
        size_t gW1 = (size_t)lr1 * 256 + kt + lc1;
        cp_async16(s + d0,             A + gA0);
        cp_async16(s + d1,             A + gA1);
        cp_async16(s + MAT_BYTES + d0, W + gW0);
        cp_async16(s + MAT_BYTES + d1, W + gW1);
    };

    const int NS = 8;
    load_stage(0, 0);
    cp_commit();

    for (int s = 0; s < NS; s++) {
        cp_wait0();
        __syncthreads();
        if (s + 1 < NS) { load_stage((s + 1) * 32, (s + 1) & 1); cp_commit(); }

        const uint32_t base = sb + (s & 1) * STAGE1;
#pragma unroll
        for (int ks = 0; ks < 2; ks++) {
            const int k0 = ks * 16;
            uint32_t fa[4][4], fb[4][2];
            load_a1_frags(base, wm, lane, k0, fa);
            load_b1_frags(base + MAT_BYTES, wn, lane, k0, fb);
            mma_block1(acc, fa, fb);
        }
    }

#pragma unroll
    for (int mi = 0; mi < 4; mi++) {
#pragma unroll
        for (int ni = 0; ni < 4; ni++) {
            int r0 = row0 + wm + mi * 16 + (lane >> 2);
            int c  = wn + ni * 8 + ((lane & 3) << 1);
            float b0 = bias[c], b1 = bias[c + 1];
            float v00 = fmaxf(acc[mi][ni][0] + b0, 0.f), v01 = fmaxf(acc[mi][ni][1] + b1, 0.f);
            float v10 = fmaxf(acc[mi][ni][2] + b0, 0.f), v11 = fmaxf(acc[mi][ni][3] + b1, 0.f);
            uint32_t hi, lo;
            split2(v00, v01, hi, lo);
            *(uint32_t*)(oh + (size_t)r0 * 128 + c) = hi;
            *(uint32_t*)(ol + (size_t)r0 * 128 + c) = lo;
            split2(v10, v11, hi, lo);
            *(uint32_t*)(oh + (size_t)(r0 + 8) * 128 + c) = hi;
            *(uint32_t*)(ol + (size_t)(r0 + 8) * 128 + c) = lo;
        }
    }
}

// ---------------- fused MLP (fp16 single) ----------------------------------------
__global__ __launch_bounds__(256)
void mlp_fused(const float* __restrict__ b1, const float* __restrict__ b2,
               float* __restrict__ out)
{
    extern __shared__ __align__(16) char smem[];
    const uint32_t sb = smem_u32(smem);

    const __half* __restrict__ Ah = g_att;
    const __half* __restrict__ W1p = g_w + 98304;
    const __half* __restrict__ W2p = g_w + 114688;

    const int tid  = threadIdx.x;
    const int lane = tid & 31;
    const int wid  = tid >> 5;
    const int wm   = (wid & 1) * 64;
    const int wn   = (wid >> 1) * 32;
    const int row0 = blockIdx.x * 128;

    const int c0 = tid * 2;
    const int lr0 = c0 >> 2,        lc0 = (c0 & 3) << 3;
    const int lr1 = (c0 + 1) >> 2,  lc1 = ((c0 + 1) & 3) << 3;

    float acc[4][4][4];
#pragma unroll
    for (int i = 0; i < 4; i++)
#pragma unroll
        for (int j = 0; j < 4; j++)
#pragma unroll
            for (int r = 0; r < 4; r++) acc[i][j][r] = 0.f;

    // ---- phase 1: h = relu(att @ W1 + b1) ----
    auto load_stage1 = [&](int kt, int buf) {
        uint32_t s = sb + buf * STAGE1;
        uint32_t d0 = (uint32_t)(lr0 * PADK + lc0) * 2;
        uint32_t d1 = (uint32_t)(lr1 * PADK + lc1) * 2;
        size_t gA0 = (size_t)(row0 + lr0) * 128 + kt + lc0;
        size_t gA1 = (size_t)(row0 + lr1) * 128 + kt + lc1;
        size_t gW0 = (size_t)lr0 * 128 + kt + lc0;
        size_t gW1 = (size_t)lr1 * 128 + kt + lc1;
        cp_async16(s + d0,             Ah + gA0);
        cp_async16(s + d1,             Ah + gA1);
        cp_async16(s + MAT_BYTES + d0, W1p + gW0);
        cp_async16(s + MAT_BYTES + d1, W1p + gW1);
    };

    load_stage1(0, 0);
    cp_commit();
    for (int s = 0; s < 4; s++) {
        cp_wait0();
        __syncthreads();
        if (s + 1 < 4) { load_stage1((s + 1) * 32, (s + 1) & 1); cp_commit(); }
        const uint32_t base = sb + (s & 1) * STAGE1;
#pragma unroll
        for (int ks = 0; ks < 2; ks++) {
            const int k0 = ks * 16;
            uint32_t fa[4][4], fb[4][2];
            load_a1_frags(base, wm, lane, k0, fa);
            load_b1_frags(base + MAT_BYTES, wn, lane, k0, fb);
            mma_block1(acc, fa, fb);
        }
    }
    __syncthreads();   // all warps done reading stage buffers before H overwrites them

    // write h (relu + b1, fp16) into SMEM H chunks: chunk kc at sb + kc*MAT_BYTES
#pragma unroll
    for (int mi = 0; mi < 4; mi++) {
#pragma unroll
        for (int ni = 0; ni < 4; ni++) {
            int r  = wm + mi * 16 + (lane >> 2);
            int c  = wn + ni * 8 + ((lane & 3) << 1);
            int kc = c >> 5, cc = c & 31;
            uint32_t hbase = sb + (uint32_t)kc * MAT_BYTES;
            float b0 = b1[c], bb1 = b1[c + 1];
            float v00 = fmaxf(acc[mi][ni][0] + b0, 0.f), v01 = fmaxf(acc[mi][ni][1] + bb1, 0.f);
            float v10 = fmaxf(acc[mi][ni][2] + b0, 0.f), v11 = fmaxf(acc[mi][ni][3] + bb1, 0.f);
            asm volatile("st.shared.b32 [%0], %1;"
                         :: "r"(hbase + (uint32_t)(r * PADK + cc) * 2), "r"(packh2(v00, v01)) : "memory");
            asm volatile("st.shared.b32 [%0], %1;"
                         :: "r"(hbase + (uint32_t)((r + 8) * PADK + cc) * 2), "r"(packh2(v10, v11)) : "memory");
        }
    }

    // ---- phase 2: out = h @ W2 + b2 ----
#pragma unroll
    for (int i = 0; i < 4; i++)
#pragma unroll
        for (int j = 0; j < 4; j++)
#pragma unroll
            for (int r = 0; r < 4; r++) acc[i][j][r] = 0.f;

    const uint32_t w2base = sb + 2 * STAGE1;   // single W2 chunk buffer
    for (int kc = 0; kc < 4; kc++) {
        {
            uint32_t d0 = (uint32_t)(lr0 * PADK + lc0) * 2;
            uint32_t d1 = (uint32_t)(lr1 * PADK + lc1) * 2;
            size_t gW0 = (size_t)lr0 * 128 + kc * 32 + lc0;
            size_t gW1 = (size_t)lr1 * 128 + kc * 32 + lc1;
            cp_async16(w2base + d0, W2p + gW0);
            cp_async16(w2base + d1, W2p + gW1);
        }
        cp_commit();
        cp_wait0();
        __syncthreads();   // W2 chunk ready; (kc=0) also orders H writes before reads

        const uint32_t hbase = sb + (uint32_t)kc * MAT_BYTES;
#pragma unroll
        for (int ks = 0; ks < 2; ks++) {
            const int k0 = ks * 16;
            uint32_t fa[4][4], fb[4][2];
            load_a1_frags(hbase, wm, lane, k0, fa);
            load_b1_frags(w2base, wn, lane, k0, fb);
            mma_block1(acc, fa, fb);
        }
        __syncthreads();   // done reading W2 buffer before next chunk overwrites
    }

#pragma unroll
    for (int mi = 0; mi < 4; mi++) {
#pragma unroll
        for (int ni = 0; ni < 4; ni++) {
            int r0 = row0 + wm + mi * 16 + (lane >> 2);
            int c  = wn + ni * 8 + ((lane & 3) << 1);
            float b0 = b2[c], bb1 = b2[c + 1];
            *(float2*)&out[(size_t)r0 * 128 + c] =
                make_float2(acc[mi][ni][0] + b0, acc[mi][ni][1] + bb1);
            *(float2*)&out[(size_t)(r0 + 8) * 128 + c] =
                make_float2(acc[mi][ni][2] + b0, acc[mi][ni][3] + bb1);
        }
    }
}

// ---------------- flash MMA attention (unchanged from R15) -----------------------
#define ATT_PAD 72
#define ATT_MAT (128 * ATT_PAD * 2)    // 18432
#define ATT_SMEM (6 * ATT_MAT)         // 110592

__global__ __launch_bounds__(384, 2)
void attn_mma()
{
    extern __shared__ __align__(16) char smem[];
    const uint32_t sb = smem_u32(smem);

    const int n  = blockIdx.x;
    const int b  = blockIdx.y;
    const int hg = blockIdx.z;
    const int tid = threadIdx.x, lane = tid & 31, wid = tid >> 5;
    const int hw  = wid & 3;
    const int grp = wid >> 2;
    const int h_global = hg * 4 + hw;

    const size_t rowbase = (size_t)(b * 128) * 256 + n;

    // ---- stage Q,K,V head-group slices (64 cols, split bf16) via cp.async ----
    {
        const __nv_bfloat16* srcs[6] = { g_q_hi, g_q_lo, g_k_hi, g_k_lo, g_v_hi, g_v_lo };
#pragma unroll
        for (int m = 0; m < 6; m++) {
            const uint16_t* __restrict__ src = (const uint16_t*)srcs[m] + hg * 64;
            uint32_t dstb = sb + (uint32_t)m * ATT_MAT;
#pragma unroll
            for (int j = 0; j < 3; j++) {
                int id = tid + j * 384;
                if (id < 1024) {
                    int row = id >> 3;
                    int c8  = (id & 7) * 8;
                    cp_async16(dstb + (uint32_t)(row * ATT_PAD + c8) * 2,
                               src + (rowbase + (size_t)row * 256) * 128 + c8);
                }
            }
        }
    }
    cp_commit();
    cp_wait0();
    __syncthreads();

    const uint32_t sqh = sb,                sql = sb + ATT_MAT;
    const uint32_t skh = sb + 2 * ATT_MAT,  skl = sb + 3 * ATT_MAT;
    const uint32_t svh = sb + 4 * ATT_MAT,  svl = sb + 5 * ATT_MAT;
    const uint32_t hoff = (uint32_t)hw * 32;

    const int g  = lane >> 2;
    const int tq = lane & 3;
    const float C = 0.36067376022224085f;    // log2(e) / sqrt(16)

    const uint32_t mtp = (grp == 0) ? 0xFF37u : (grp == 1) ? 0xFF46u : 0x0125u;

    for (int ii = 0; ii < 4; ii++) {
        const int mt = (int)((mtp >> (ii * 4)) & 0xFu);
        if (mt == 15) break;

        uint32_t qh[4], ql[4];
        {
            uint32_t off = (uint32_t)((mt * 16 + (lane & 15)) * ATT_PAD) * 2
                           + hoff + (uint32_t)((lane >> 4) << 4);
            ldmatrix_x4(qh, sqh + off);
            ldmatrix_x4(ql, sql + off);
        }

        float o0[4] = {0.f, 0.f, 0.f, 0.f};
        float o1[4] = {0.f, 0.f, 0.f, 0.f};
        float m0 = -1e30f, m1 = -1e30f, sum0 = 0.f, sum1 = 0.f;
        const int p0 = mt * 16 + g, p1 = p0 + 8;

        for (int c = 0; c <= mt; c++) {
            float S0[4] = {0.f, 0.f, 0.f, 0.f};
            float S1[4] = {0.f, 0.f, 0.f, 0.f};
            {
                uint32_t off = (uint32_t)((c * 16 + ((lane >> 4) << 3) + (lane & 7)) * ATT_PAD) * 2
                               + hoff + (uint32_t)(((lane >> 3) & 1) << 4);
                uint32_t t[4], kh0[2], kh1[2], kl0[2], kl1[2];
                ldmatrix_x4(t, skh + off);
                kh0[0] = t[0]; kh0[1] = t[1]; kh1[0] = t[2]; kh1[1] = t[3];
                ldmatrix_x4(t, skl + off);
                kl0[0] = t[0]; kl0[1] = t[1]; kl1[0] = t[2]; kl1[1] = t[3];
                mma_bf16(S0, qh, kh0); mma_bf16(S0, qh, kl0); mma_bf16(S0, ql, kh0);
                mma_bf16(S1, qh, kh1); mma_bf16(S1, qh, kl1); mma_bf16(S1, ql, kh1);
            }

            if (c == mt) {
                int ka = c * 16 + tq * 2;
                if (ka     > p0) S0[0] = -1e30f;
                if (ka + 1 > p0) S0[1] = -1e30f;
                if (ka     > p1) S0[2] = -1e30f;
                if (ka + 1 > p1) S0[3] = -1e30f;
                if (ka + 8 > p0) S1[0] = -1e30f;
                if (ka + 9 > p0) S1[1] = -1e30f;
                if (ka + 8 > p1) S1[2] = -1e30f;
                if (ka + 9 > p1) S1[3] = -1e30f;
            }

            float t0 = fmaxf(fmaxf(S0[0], S0[1]), fmaxf(S1[0], S1[1]));
            float t1 = fmaxf(fmaxf(S0[2], S0[3]), fmaxf(S1[2], S1[3]));
            t0 = fmaxf(t0, __shfl_xor_sync(0xffffffffu, t0, 1));
            t0 = fmaxf(t0, __shfl_xor_sync(0xffffffffu, t0, 2));
            t1 = fmaxf(t1, __shfl_xor_sync(0xffffffffu, t1, 1));
            t1 = fmaxf(t1, __shfl_xor_sync(0xffffffffu, t1, 2));

            float nm0 = fmaxf(m0, t0), nm1 = fmaxf(m1, t1);
            float r0 = ex2f((m0 - nm0) * C), r1 = ex2f((m1 - nm1) * C);
            m0 = nm0; m1 = nm1;
            sum0 *= r0; sum1 *= r1;
            o0[0] *= r0; o0[1] *= r0; o1[0] *= r0; o1[1] *= r0;
            o0[2] *= r1; o0[3] *= r1; o1[2] *= r1; o1[3] *= r1;

            S0[0] = ex2f((S0[0] - m0) * C); S0[1] = ex2f((S0[1] - m0) * C);
            S0[2] = ex2f((S0[2] - m1) * C); S0[3] = ex2f((S0[3] - m1) * C);
            S1[0] = ex2f((S1[0] - m0) * C); S1[1] = ex2f((S1[1] - m0) * C);
            S1[2] = ex2f((S1[2] - m1) * C); S1[3] = ex2f((S1[3] - m1) * C);
            sum0 += S0[0] + S0[1] + S1[0] + S1[1];
            sum1 += S0[2] + S0[3] + S1[2] + S1[3];

            uint32_t ph[4], pl[4];
            split2(S0[0], S0[1], ph[0], pl[0]);
            split2(S0[2], S0[3], ph[1], pl[1]);
            split2(S1[0], S1[1], ph[2], pl[2]);
            split2(S1[2], S1[3], ph[3], pl[3]);
            {
                uint32_t off = (uint32_t)((c * 16 + (((lane >> 3) & 1) << 3) + (lane & 7)) * ATT_PAD) * 2
                               + hoff + (uint32_t)((lane >> 4) << 4);
                uint32_t t[4], vh0[2], vh1[2], vl0[2], vl1[2];
                ldmatrix_x4t(t, svh + off);
                vh0[0] = t[0]; vh0[1] = t[1]; vh1[0] = t[2]; vh1[1] = t[3];
                ldmatrix_x4t(t, svl + off);
                vl0[0] = t[0]; vl0[1] = t[1]; vl1[0] = t[2]; vl1[1] = t[3];
                mma_bf16(o0, ph, vh0); mma_bf16(o0, ph, vl0); mma_bf16(o0, pl, vh0);
                mma_bf16(o1, ph, vh1); mma_bf16(o1, ph, vl1); mma_bf16(o1, pl, vh1);
            }
        }

        sum0 += __shfl_xor_sync(0xffffffffu, sum0, 1);
        sum0 += __shfl_xor_sync(0xffffffffu, sum0, 2);
        sum1 += __shfl_xor_sync(0xffffffffu, sum1, 1);
        sum1 += __shfl_xor_sync(0xffffffffu, sum1, 2);
        const float inv0 = 1.f / sum0, inv1 = 1.f / sum1;

        const size_t r0b = (rowbase + (size_t)p0 * 256) * 128 + h_global * 16 + tq * 2;
        const size_t r1b = (rowbase + (size_t)p1 * 256) * 128 + h_global * 16 + tq * 2;
        *(uint32_t*)((uint16_t*)g_att + r0b)     = packh2(o0[0] * inv0, o0[1] * inv0);
        *(uint32_t*)((uint16_t*)g_att + r1b)     = packh2(o0[2] * inv1, o0[3] * inv1);
        *(uint32_t*)((uint16_t*)g_att + r0b + 8) = packh2(o1[0] * inv0, o1[1] * inv0);
        *(uint32_t*)((uint16_t*)g_att + r1b + 8) = packh2(o1[2] * inv1, o1[3] * inv1);
    }
}

// ---------------- launch -------------------------------------------------------
extern "C" void kernel_launch(void* const* d_in, const int* in_sizes, int n_in,
                              void* d_out, int out_size)
{
    const float* X   = (const float*)d_in[0];
    const float* STE = (const float*)d_in[1];
    const float* Wq  = (const float*)d_in[2];
    const float* bq  = (const float*)d_in[3];
    const float* Wk  = (const float*)d_in[4];
    const float* bk  = (const float*)d_in[5];
    const float* Wv  = (const float*)d_in[6];
    const float* bv  = (const float*)d_in[7];
    const float* W1  = (const float*)d_in[8];
    const float* b1  = (const float*)d_in[9];
    const float* W2  = (const float*)d_in[10];
    const float* b2  = (const float*)d_in[11];
    float* out = (float*)d_out;

    cudaFuncSetAttribute(qkv_gemm,  cudaFuncAttributeMaxDynamicSharedMemorySize, QKV_SMEM);
    cudaFuncSetAttribute(mlp_fused, cudaFuncAttributeMaxDynamicSharedMemorySize, MLP_SMEM);
    cudaFuncSetAttribute(attn_mma,  cudaFuncAttributeMaxDynamicSharedMemorySize, ATT_SMEM);

    // preprocessing: weight transpose+fp16, activation concat+fp16
    convert_w<<<512, 256>>>(Wq, Wk, Wv, W1, W2);
    convert_a<<<32768, 256>>>(X, STE);

    // fused QKV projections (fp16 single; x = weight select -> L2-shared A tiles)
    qkv_gemm<<<dim3(3, M_ / 128), 256, QKV_SMEM>>>(bq, bk, bv);

    // flash MMA attention: block per (n, b, head-group), 12 warps
    attn_mma<<<dim3(N_, B_, 2), 384, ATT_SMEM>>>();

    // fused output MLP (fp16 single)
    mlp_fused<<<M_ / 128, 256, MLP_SMEM>>>(b1, b2, out);
}

// round 17
// speedup vs baseline: 2.4361x; 1.1740x over previous
#include <cuda_runtime.h>
#include <cuda_bf16.h>
#include <cuda_fp16.h>
#include <math.h>
#include <stdint.h>

#define B_   8
#define P_   128
#define N_   256
#define D_   128
#define M_   (B_*P_*N_)        // 262144 rows

// ---------------- scratch (device globals; no allocation allowed) ----------------
__device__ __align__(16) __half g_a[(size_t)M_ * 256];            // fp16 concat(X,STE)
__device__ __align__(16) __nv_bfloat16 g_q_hi[(size_t)M_ * D_];   // Q/K: split bf16 (softmax precision)
__device__ __align__(16) __nv_bfloat16 g_q_lo[(size_t)M_ * D_];
__device__ __align__(16) __nv_bfloat16 g_k_hi[(size_t)M_ * D_];
__device__ __align__(16) __nv_bfloat16 g_k_lo[(size_t)M_ * D_];
__device__ __align__(16) __half g_v[(size_t)M_ * D_];             // V: fp16 single
__device__ __align__(16) __half g_att[(size_t)M_ * D_];           // fp16 attention output
// weights transposed to [n][k], fp16. layout: Wq(32768) Wk Wv W1(16384) W2
__device__ __align__(16) __half g_w[131072];

// ---------------- helpers ----------------
__device__ __forceinline__ uint32_t smem_u32(const void* p) {
    uint32_t a;
    asm("{ .reg .u64 t; cvta.to.shared.u64 t, %1; cvt.u32.u64 %0, t; }" : "=r"(a) : "l"(p));
    return a;
}
// bf16 split (attention Q/K path)
__device__ __forceinline__ void split_bf16(float x, uint16_t& h, uint16_t& l) {
    __nv_bfloat16 hb = __float2bfloat16(x);
    __nv_bfloat16 lb = __float2bfloat16(x - __bfloat162float(hb));
    h = __bfloat16_as_ushort(hb);
    l = __bfloat16_as_ushort(lb);
}
__device__ __forceinline__ void split2(float a, float b, uint32_t& hi, uint32_t& lo) {
    uint16_t ha, la, hb, lb;
    split_bf16(a, ha, la);
    split_bf16(b, hb, lb);
    hi = (uint32_t)ha | ((uint32_t)hb << 16);
    lo = (uint32_t)la | ((uint32_t)lb << 16);
}
// fp16 helpers
__device__ __forceinline__ uint32_t packh2(float a, float b) {
    __half2 h = __floats2half2_rn(a, b);
    return *(uint32_t*)&h;
}
__device__ __forceinline__ float ex2f(float x) {
    float y; asm("ex2.approx.f32 %0, %1;" : "=f"(y) : "f"(x)); return y;
}
__device__ __forceinline__ void ldmatrix_x4(uint32_t* r, uint32_t addr) {
    asm volatile("ldmatrix.sync.aligned.m8n8.x4.shared.b16 {%0,%1,%2,%3}, [%4];"
                 : "=r"(r[0]), "=r"(r[1]), "=r"(r[2]), "=r"(r[3]) : "r"(addr));
}
__device__ __forceinline__ void ldmatrix_x4t(uint32_t* r, uint32_t addr) {
    asm volatile("ldmatrix.sync.aligned.m8n8.x4.trans.shared.b16 {%0,%1,%2,%3}, [%4];"
                 : "=r"(r[0]), "=r"(r[1]), "=r"(r[2]), "=r"(r[3]) : "r"(addr));
}
__device__ __forceinline__ void mma_bf16(float* d, const uint32_t* a, const uint32_t* b) {
    asm volatile(
        "mma.sync.aligned.m16n8k16.row.col.f32.bf16.bf16.f32 "
        "{%0,%1,%2,%3}, {%4,%5,%6,%7}, {%8,%9}, {%0,%1,%2,%3};"
        : "+f"(d[0]), "+f"(d[1]), "+f"(d[2]), "+f"(d[3])
        : "r"(a[0]), "r"(a[1]), "r"(a[2]), "r"(a[3]), "r"(b[0]), "r"(b[1]));
}
__device__ __forceinline__ void mma_f16(float* d, const uint32_t* a, const uint32_t* b) {
    asm volatile(
        "mma.sync.aligned.m16n8k16.row.col.f32.f16.f16.f32 "
        "{%0,%1,%2,%3}, {%4,%5,%6,%7}, {%8,%9}, {%0,%1,%2,%3};"
        : "+f"(d[0]), "+f"(d[1]), "+f"(d[2]), "+f"(d[3])
        : "r"(a[0]), "r"(a[1]), "r"(a[2]), "r"(a[3]), "r"(b[0]), "r"(b[1]));
}
__device__ __forceinline__ void cp_async16(uint32_t dst, const void* src) {
    asm volatile("cp.async.cg.shared.global [%0], [%1], 16;" :: "r"(dst), "l"(src));
}
__device__ __forceinline__ void cp_commit() {
    asm volatile("cp.async.commit_group;" ::: "memory");
}
__device__ __forceinline__ void cp_wait0() {
    asm volatile("cp.async.wait_group 0;" ::: "memory");
}

// ---------------- convert weights: W[k][n] fp32 -> transposed fp16 ---------------
__global__ void convert_w(const float* __restrict__ Wq, const float* __restrict__ Wk,
                          const float* __restrict__ Wv, const float* __restrict__ W1,
                          const float* __restrict__ W2)
{
    int id = blockIdx.x * 256 + threadIdx.x;      // < 131072
    const float* src; int K, n, k; size_t dofs;
    if (id < 98304) {
        int wi = id >> 15, rem = id & 32767;
        k = rem >> 7; n = rem & 127; K = 256;
        src = (wi == 0) ? Wq : (wi == 1) ? Wk : Wv;
        dofs = (size_t)wi * 32768;
    } else {
        int r2 = id - 98304;
        int wi = r2 >> 14, rem = r2 & 16383;
        k = rem >> 7; n = rem & 127; K = 128;
        src = wi ? W2 : W1;
        dofs = 98304 + (size_t)wi * 16384;
    }
    float x = src[(size_t)k * 128 + n];
    ((uint16_t*)g_w)[dofs + (size_t)n * K + k] = __half_as_ushort(__float2half_rn(x));
}

// ---------------- convert activations: concat(X,STE) -> fp16 [M x 256] -----------
__global__ void convert_a(const float* __restrict__ X, const float* __restrict__ STE)
{
    size_t id = (size_t)blockIdx.x * 256 + threadIdx.x;   // one per 8 elements
    int row = (int)(id >> 5);
    int c8  = (int)(id & 31) << 3;
    const float* src = (c8 < 128) ? (X + (size_t)row * 128 + c8)
                                  : (STE + (size_t)row * 128 + (c8 - 128));
    float4 v0 = ((const float4*)src)[0];
    float4 v1 = ((const float4*)src)[1];
    uint4 o;
    o.x = packh2(v0.x, v0.y);
    o.y = packh2(v0.z, v0.w);
    o.z = packh2(v1.x, v1.y);
    o.w = packh2(v1.z, v1.w);
    *(uint4*)((uint16_t*)g_a + (size_t)row * 256 + c8) = o;
}

// ---------------- shared GEMM tile constants ------------------------------------
#define PADK 40                       // 80B row stride: 16B-aligned, ldmatrix conflict-free
#define MAT_BYTES (128 * PADK * 2)    // 10240
#define STAGE1 (2 * MAT_BYTES)        // 20480: [A | W]
#define MLP_SMEM (2 * STAGE1 + MAT_BYTES)   // 51200

__device__ __forceinline__ void load_b1_frags(uint32_t base, int wn, int lane, int k0,
                                              uint32_t fb[4][2]) {
#pragma unroll
    for (int njp = 0; njp < 2; njp++) {
        uint32_t off = (uint32_t)((wn + njp * 16 + ((lane >> 4) << 3) + (lane & 7)) * PADK
                                  + k0 + (((lane >> 3) & 1) << 3)) * 2;
        uint32_t t[4];
        ldmatrix_x4(t, base + off);
        fb[2*njp][0] = t[0]; fb[2*njp][1] = t[1];
        fb[2*njp+1][0] = t[2]; fb[2*njp+1][1] = t[3];
    }
}
__device__ __forceinline__ void mma_block1(float acc[4][4][4],
                                           uint32_t fa[4][4], uint32_t fb[4][2]) {
#pragma unroll
    for (int mi = 0; mi < 4; mi++)
#pragma unroll
        for (int ni = 0; ni < 4; ni++)
            mma_f16(acc[mi][ni], fa[mi], fb[ni]);
}

// ---------------- A-resident fused QKV (fp16) ------------------------------------
// One CTA per 128-row block. Phase 0: cp.async the full [128x256] fp16 A tile into
// resident smem (PADA=264 -> 528B rows, conflict-free ldmatrix). Then 24 flat
// stages (3 weights x 8 k-chunks) with double-buffered W. Epilogue per weight:
// Q/K split-bf16, V fp16 single.
#define PADA 264
#define ARES_BYTES (128 * PADA * 2)              // 67584
#define QKVF_SMEM (ARES_BYTES + 2 * MAT_BYTES)   // 88064

__global__ __launch_bounds__(256, 2)
void qkv_fused(const float* __restrict__ bq, const float* __restrict__ bk,
               const float* __restrict__ bv)
{
    extern __shared__ __align__(16) char smem[];
    const uint32_t sb = smem_u32(smem);
    const int tid  = threadIdx.x;
    const int lane = tid & 31;
    const int wid  = tid >> 5;
    const int wm   = (wid & 1) * 64;
    const int wn   = (wid >> 1) * 32;
    const int row0 = blockIdx.x * 128;

    // ---- phase 0: resident A tile via cp.async (4096 16B chunks, 16/thread) ----
#pragma unroll
    for (int i = 0; i < 16; i++) {
        int id = tid + i * 256;
        int r  = id >> 5;
        int c8 = (id & 31) * 8;
        cp_async16(sb + (uint32_t)(r * PADA + c8) * 2,
                   (const uint16_t*)g_a + (size_t)(row0 + r) * 256 + c8);
    }

    // ---- W chunk loader: [128 n][32 k] fp16 = 10240 B (2 chunks/thread) ----
    const int c0 = tid * 2;
    const int lr0 = c0 >> 2,        lc0 = (c0 & 3) << 3;
    const int lr1 = (c0 + 1) >> 2,  lc1 = ((c0 + 1) & 3) << 3;
    auto load_w = [&](int st) {
        const int wsel = st >> 3, kt = (st & 7) * 32;
        const __half* W = g_w + wsel * 32768;
        uint32_t s = sb + ARES_BYTES + (st & 1) * MAT_BYTES;
        cp_async16(s + (uint32_t)(lr0 * PADK + lc0) * 2, W + (size_t)lr0 * 256 + kt + lc0);
        cp_async16(s + (uint32_t)(lr1 * PADK + lc1) * 2, W + (size_t)lr1 * 256 + kt + lc1);
    };

    float acc[4][4][4];
#pragma unroll
    for (int i = 0; i < 4; i++)
#pragma unroll
        for (int j = 0; j < 4; j++)
#pragma unroll
            for (int r = 0; r < 4; r++) acc[i][j][r] = 0.f;

    load_w(0);
    cp_commit();   // one group: A tile + W chunk 0

    for (int st = 0; st < 24; st++) {
        cp_wait0();
        __syncthreads();
        if (st + 1 < 24) { load_w(st + 1); cp_commit(); }

        const uint32_t wbase = sb + ARES_BYTES + (st & 1) * MAT_BYTES;
        const int kt = (st & 7) * 32;
#pragma unroll
        for (int ks = 0; ks < 2; ks++) {
            const int k0a = kt + ks * 16;
            uint32_t fa[4][4];
#pragma unroll
            for (int mi = 0; mi < 4; mi++) {
                uint32_t off = (uint32_t)((wm + mi * 16 + (lane & 15)) * PADA
                                          + k0a + ((lane >> 4) << 3)) * 2;
                ldmatrix_x4(fa[mi], sb + off);
            }
            uint32_t fb[4][2];
            load_b1_frags(wbase, wn, lane, ks * 16, fb);
            mma_block1(acc, fa, fb);
        }

        if ((st & 7) == 7) {
            const int wsel = st >> 3;
            const float* __restrict__ bias = (wsel == 0) ? bq : (wsel == 1) ? bk : bv;
#pragma unroll
            for (int mi = 0; mi < 4; mi++) {
#pragma unroll
                for (int ni = 0; ni < 4; ni++) {
                    int r0 = row0 + wm + mi * 16 + (lane >> 2);
                    int c  = wn + ni * 8 + ((lane & 3) << 1);
                    float b0 = bias[c], b1 = bias[c + 1];
                    float v00 = fmaxf(acc[mi][ni][0] + b0, 0.f), v01 = fmaxf(acc[mi][ni][1] + b1, 0.f);
                    float v10 = fmaxf(acc[mi][ni][2] + b0, 0.f), v11 = fmaxf(acc[mi][ni][3] + b1, 0.f);
                    if (wsel < 2) {
                        uint16_t* oh = (uint16_t*)(wsel == 0 ? g_q_hi : g_k_hi);
                        uint16_t* ol = (uint16_t*)(wsel == 0 ? g_q_lo : g_k_lo);
                        uint32_t hi, lo;
                        split2(v00, v01, hi, lo);
                        *(uint32_t*)(oh + (size_t)r0 * 128 + c) = hi;
                        *(uint32_t*)(ol + (size_t)r0 * 128 + c) = lo;
                        split2(v10, v11, hi, lo);
                        *(uint32_t*)(oh + (size_t)(r0 + 8) * 128 + c) = hi;
                        *(uint32_t*)(ol + (size_t)(r0 + 8) * 128 + c) = lo;
                    } else {
                        *(uint32_t*)((uint16_t*)g_v + (size_t)r0 * 128 + c)       = packh2(v00, v01);
                        *(uint32_t*)((uint16_t*)g_v + (size_t)(r0 + 8) * 128 + c) = packh2(v10, v11);
                    }
                    acc[mi][ni][0] = 0.f; acc[mi][ni][1] = 0.f;
                    acc[mi][ni][2] = 0.f; acc[mi][ni][3] = 0.f;
                }
            }
        }
    }
}

// ---------------- fused MLP (fp16 single; unchanged from R16) ---------------------
__global__ __launch_bounds__(256)
void mlp_fused(const float* __restrict__ b1, const float* __restrict__ b2,
               float* __restrict__ out)
{
    extern __shared__ __align__(16) char smem[];
    const uint32_t sb = smem_u32(smem);

    const __half* __restrict__ Ah = g_att;
    const __half* __restrict__ W1p = g_w + 98304;
    const __half* __restrict__ W2p = g_w + 114688;

    const int tid  = threadIdx.x;
    const int lane = tid & 31;
    const int wid  = tid >> 5;
    const int wm   = (wid & 1) * 64;
    const int wn   = (wid >> 1) * 32;
    const int row0 = blockIdx.x * 128;

    const int c0 = tid * 2;
    const int lr0 = c0 >> 2,        lc0 = (c0 & 3) << 3;
    const int lr1 = (c0 + 1) >> 2,  lc1 = ((c0 + 1) & 3) << 3;

    float acc[4][4][4];
#pragma unroll
    for (int i = 0; i < 4; i++)
#pragma unroll
        for (int j = 0; j < 4; j++)
#pragma unroll
            for (int r = 0; r < 4; r++) acc[i][j][r] = 0.f;

    auto load_a1_frags = [&](uint32_t base, int k0, uint32_t fa[4][4]) {
#pragma unroll
        for (int mi = 0; mi < 4; mi++) {
            uint32_t off = (uint32_t)((wm + mi * 16 + (lane & 15)) * PADK
                                      + k0 + ((lane >> 4) << 3)) * 2;
            ldmatrix_x4(fa[mi], base + off);
        }
    };

    // ---- phase 1: h = relu(att @ W1 + b1) ----
    auto load_stage1 = [&](int kt, int buf) {
        uint32_t s = sb + buf * STAGE1;
        uint32_t d0 = (uint32_t)(lr0 * PADK + lc0) * 2;
        uint32_t d1 = (uint32_t)(lr1 * PADK + lc1) * 2;
        size_t gA0 = (size_t)(row0 + lr0) * 128 + kt + lc0;
        size_t gA1 = (size_t)(row0 + lr1) * 128 + kt + lc1;
        size_t gW0 = (size_t)lr0 * 128 + kt + lc0;
        size_t gW1 = (size_t)lr1 * 128 + kt + lc1;
        cp_async16(s + d0,             Ah + gA0);
        cp_async16(s + d1,             Ah + gA1);
        cp_async16(s + MAT_BYTES + d0, W1p + gW0);
        cp_async16(s + MAT_BYTES + d1, W1p + gW1);
    };

    load_stage1(0, 0);
    cp_commit();
    for (int s = 0; s < 4; s++) {
        cp_wait0();
        __syncthreads();
        if (s + 1 < 4) { load_stage1((s + 1) * 32, (s + 1) & 1); cp_commit(); }
        const uint32_t base = sb + (s & 1) * STAGE1;
#pragma unroll
        for (int ks = 0; ks < 2; ks++) {
            const int k0 = ks * 16;
            uint32_t fa[4][4], fb[4][2];
            load_a1_frags(base, k0, fa);
            load_b1_frags(base + MAT_BYTES, wn, lane, k0, fb);
            mma_block1(acc, fa, fb);
        }
    }
    __syncthreads();

#pragma unroll
    for (int mi = 0; mi < 4; mi++) {
#pragma unroll
        for (int ni = 0; ni < 4; ni++) {
            int r  = wm + mi * 16 + (lane >> 2);
            int c  = wn + ni * 8 + ((lane & 3) << 1);
            int kc = c >> 5, cc = c & 31;
            uint32_t hbase = sb + (uint32_t)kc * MAT_BYTES;
            float b0 = b1[c], bb1 = b1[c + 1];
            float v00 = fmaxf(acc[mi][ni][0] + b0, 0.f), v01 = fmaxf(acc[mi][ni][1] + bb1, 0.f);
            float v10 = fmaxf(acc[mi][ni][2] + b0, 0.f), v11 = fmaxf(acc[mi][ni][3] + bb1, 0.f);
            asm volatile("st.shared.b32 [%0], %1;"
                         :: "r"(hbase + (uint32_t)(r * PADK + cc) * 2), "r"(packh2(v00, v01)) : "memory");
            asm volatile("st.shared.b32 [%0], %1;"
                         :: "r"(hbase + (uint32_t)((r + 8) * PADK + cc) * 2), "r"(packh2(v10, v11)) : "memory");
        }
    }

    // ---- phase 2: out = h @ W2 + b2 ----
#pragma unroll
    for (int i = 0; i < 4; i++)
#pragma unroll
        for (int j = 0; j < 4; j++)
#pragma unroll
            for (int r = 0; r < 4; r++) acc[i][j][r] = 0.f;

    const uint32_t w2base = sb + 2 * STAGE1;
    for (int kc = 0; kc < 4; kc++) {
        {
            uint32_t d0 = (uint32_t)(lr0 * PADK + lc0) * 2;
            uint32_t d1 = (uint32_t)(lr1 * PADK + lc1) * 2;
            size_t gW0 = (size_t)lr0 * 128 + kc * 32 + lc0;
            size_t gW1 = (size_t)lr1 * 128 + kc * 32 + lc1;
            cp_async16(w2base + d0, W2p + gW0);
            cp_async16(w2base + d1, W2p + gW1);
        }
        cp_commit();
        cp_wait0();
        __syncthreads();

        const uint32_t hbase = sb + (uint32_t)kc * MAT_BYTES;
#pragma unroll
        for (int ks = 0; ks < 2; ks++) {
            const int k0 = ks * 16;
            uint32_t fa[4][4], fb[4][2];
            load_a1_frags(hbase, k0, fa);
            load_b1_frags(w2base, wn, lane, k0, fb);
            mma_block1(acc, fa, fb);
        }
        __syncthreads();
    }

#pragma unroll
    for (int mi = 0; mi < 4; mi++) {
#pragma unroll
        for (int ni = 0; ni < 4; ni++) {
            int r0 = row0 + wm + mi * 16 + (lane >> 2);
            int c  = wn + ni * 8 + ((lane & 3) << 1);
            float b0 = b2[c], bb1 = b2[c + 1];
            *(float2*)&out[(size_t)r0 * 128 + c] =
                make_float2(acc[mi][ni][0] + b0, acc[mi][ni][1] + bb1);
            *(float2*)&out[(size_t)(r0 + 8) * 128 + c] =
                make_float2(acc[mi][ni][2] + b0, acc[mi][ni][3] + bb1);
        }
    }
}

// ---------------- flash MMA attention (fp16 P·V) ---------------------------------
// Q/K: split-bf16 3-term QK (softmax precision). P and V: fp16 single -> PV is
// 2 MMAs per key tile (was 6) and 1 trans-ldmatrix (was 2); P packing via packh2.
#define ATT_PAD 72
#define ATT_MAT (128 * ATT_PAD * 2)    // 18432
#define ATT_SMEM (5 * ATT_MAT)         // 92160

__global__ __launch_bounds__(384, 2)
void attn_mma()
{
    extern __shared__ __align__(16) char smem[];
    const uint32_t sb = smem_u32(smem);

    const int n  = blockIdx.x;
    const int b  = blockIdx.y;
    const int hg = blockIdx.z;
    const int tid = threadIdx.x, lane = tid & 31, wid = tid >> 5;
    const int hw  = wid & 3;
    const int grp = wid >> 2;
    const int h_global = hg * 4 + hw;

    const size_t rowbase = (size_t)(b * 128) * 256 + n;

    // ---- stage Q,K (split bf16) + V (fp16) head-group slices via cp.async ----
    {
        const void* srcs[5] = { g_q_hi, g_q_lo, g_k_hi, g_k_lo, g_v };
#pragma unroll
        for (int m = 0; m < 5; m++) {
            const uint16_t* __restrict__ src = (const uint16_t*)srcs[m] + hg * 64;
            uint32_t dstb = sb + (uint32_t)m * ATT_MAT;
#pragma unroll
            for (int j = 0; j < 3; j++) {
                int id = tid + j * 384;
                if (id < 1024) {
                    int row = id >> 3;
                    int c8  = (id & 7) * 8;
                    cp_async16(dstb + (uint32_t)(row * ATT_PAD + c8) * 2,
                               src + (rowbase + (size_t)row * 256) * 128 + c8);
                }
            }
        }
    }
    cp_commit();
    cp_wait0();
    __syncthreads();

    const uint32_t sqh = sb,                sql = sb + ATT_MAT;
    const uint32_t skh = sb + 2 * ATT_MAT,  skl = sb + 3 * ATT_MAT;
    const uint32_t sv  = sb + 4 * ATT_MAT;
    const uint32_t hoff = (uint32_t)hw * 32;

    const int g  = lane >> 2;
    const int tq = lane & 3;
    const float C = 0.36067376022224085f;    // log2(e) / sqrt(16)

    const uint32_t mtp = (grp == 0) ? 0xFF37u : (grp == 1) ? 0xFF46u : 0x0125u;

    for (int ii = 0; ii < 4; ii++) {
        const int mt = (int)((mtp >> (ii * 4)) & 0xFu);
        if (mt == 15) break;

        uint32_t qh[4], ql[4];
        {
            uint32_t off = (uint32_t)((mt * 16 + (lane & 15)) * ATT_PAD) * 2
                           + hoff + (uint32_t)((lane >> 4) << 4);
            ldmatrix_x4(qh, sqh + off);
            ldmatrix_x4(ql, sql + off);
        }

        float o0[4] = {0.f, 0.f, 0.f, 0.f};
        float o1[4] = {0.f, 0.f, 0.f, 0.f};
        float m0 = -1e30f, m1 = -1e30f, sum0 = 0.f, sum1 = 0.f;
        const int p0 = mt * 16 + g, p1 = p0 + 8;

        for (int c = 0; c <= mt; c++) {
            float S0[4] = {0.f, 0.f, 0.f, 0.f};
            float S1[4] = {0.f, 0.f, 0.f, 0.f};
            {
                uint32_t off = (uint32_t)((c * 16 + ((lane >> 4) << 3) + (lane & 7)) * ATT_PAD) * 2
                               + hoff + (uint32_t)(((lane >> 3) & 1) << 4);
                uint32_t t[4], kh0[2], kh1[2], kl0[2], kl1[2];
                ldmatrix_x4(t, skh + off);
                kh0[0] = t[0]; kh0[1] = t[1]; kh1[0] = t[2]; kh1[1] = t[3];
                ldmatrix_x4(t, skl + off);
                kl0[0] = t[0]; kl0[1] = t[1]; kl1[0] = t[2]; kl1[1] = t[3];
                mma_bf16(S0, qh, kh0); mma_bf16(S0, qh, kl0); mma_bf16(S0, ql, kh0);
                mma_bf16(S1, qh, kh1); mma_bf16(S1, qh, kl1); mma_bf16(S1, ql, kh1);
            }

            if (c == mt) {
                int ka = c * 16 + tq * 2;
                if (ka     > p0) S0[0] = -1e30f;
                if (ka + 1 > p0) S0[1] = -1e30f;
                if (ka     > p1) S0[2] = -1e30f;
                if (ka + 1 > p1) S0[3] = -1e30f;
                if (ka + 8 > p0) S1[0] = -1e30f;
                if (ka + 9 > p0) S1[1] = -1e30f;
                if (ka + 8 > p1) S1[2] = -1e30f;
                if (ka + 9 > p1) S1[3] = -1e30f;
            }

            float t0 = fmaxf(fmaxf(S0[0], S0[1]), fmaxf(S1[0], S1[1]));
            float t1 = fmaxf(fmaxf(S0[2], S0[3]), fmaxf(S1[2], S1[3]));
            t0 = fmaxf(t0, __shfl_xor_sync(0xffffffffu, t0, 1));
            t0 = fmaxf(t0, __shfl_xor_sync(0xffffffffu, t0, 2));
            t1 = fmaxf(t1, __shfl_xor_sync(0xffffffffu, t1, 1));
            t1 = fmaxf(t1, __shfl_xor_sync(0xffffffffu, t1, 2));

            float nm0 = fmaxf(m0, t0), nm1 = fmaxf(m1, t1);
            float r0 = ex2f((m0 - nm0) * C), r1 = ex2f((m1 - nm1) * C);
            m0 = nm0; m1 = nm1;
            sum0 *= r0; sum1 *= r1;
            o0[0] *= r0; o0[1] *= r0; o1[0] *= r0; o1[1] *= r0;
            o0[2] *= r1; o0[3] *= r1; o1[2] *= r1; o1[3] *= r1;

            S0[0] = ex2f((S0[0] - m0) * C); S0[1] = ex2f((S0[1] - m0) * C);
            S0[2] = ex2f((S0[2] - m1) * C); S0[3] = ex2f((S0[3] - m1) * C);
            S1[0] = ex2f((S1[0] - m0) * C); S1[1] = ex2f((S1[1] - m0) * C);
            S1[2] = ex2f((S1[2] - m1) * C); S1[3] = ex2f((S1[3] - m1) * C);
            sum0 += S0[0] + S0[1] + S1[0] + S1[1];
            sum1 += S0[2] + S0[3] + S1[2] + S1[3];

            // fp16 P fragments + fp16 V: 2 MMAs per tile
            uint32_t pf[4];
            pf[0] = packh2(S0[0], S0[1]);
            pf[1] = packh2(S0[2], S0[3]);
            pf[2] = packh2(S1[0], S1[1]);
            pf[3] = packh2(S1[2], S1[3]);
            {
                uint32_t off = (uint32_t)((c * 16 + (((lane >> 3) & 1) << 3) + (lane & 7)) * ATT_PAD) * 2
                               + hoff + (uint32_t)((lane >> 4) << 4);
                uint32_t t[4];
                ldmatrix_x4t(t, sv + off);
                uint32_t v0[2] = { t[0], t[1] };
                uint32_t v1[2] = { t[2], t[3] };
                mma_f16(o0, pf, v0);
                mma_f16(o1, pf, v1);
            }
        }

        sum0 += __shfl_xor_sync(0xffffffffu, sum0, 1);
        sum0 += __shfl_xor_sync(0xffffffffu, sum0, 2);
        sum1 += __shfl_xor_sync(0xffffffffu, sum1, 1);
        sum1 += __shfl_xor_sync(0xffffffffu, sum1, 2);
        const float inv0 = 1.f / sum0, inv1 = 1.f / sum1;

        const size_t r0b = (rowbase + (size_t)p0 * 256) * 128 + h_global * 16 + tq * 2;
        const size_t r1b = (rowbase + (size_t)p1 * 256) * 128 + h_global * 16 + tq * 2;
        *(uint32_t*)((uint16_t*)g_att + r0b)     = packh2(o0[0] * inv0, o0[1] * inv0);
        *(uint32_t*)((uint16_t*)g_att + r1b)     = packh2(o0[2] * inv1, o0[3] * inv1);
        *(uint32_t*)((uint16_t*)g_att + r0b + 8) = packh2(o1[0] * inv0, o1[1] * inv0);
        *(uint32_t*)((uint16_t*)g_att + r1b + 8) = packh2(o1[2] * inv1, o1[3] * inv1);
    }
}

// ---------------- launch -------------------------------------------------------
extern "C" void kernel_launch(void* const* d_in, const int* in_sizes, int n_in,
                              void* d_out, int out_size)
{
    const float* X   = (const float*)d_in[0];
    const float* STE = (const float*)d_in[1];
    const float* Wq  = (const float*)d_in[2];
    const float* bq  = (const float*)d_in[3];
    const float* Wk  = (const float*)d_in[4];
    const float* bk  = (const float*)d_in[5];
    const float* Wv  = (const float*)d_in[6];
    const float* bv  = (const float*)d_in[7];
    const float* W1  = (const float*)d_in[8];
    const float* b1  = (const float*)d_in[9];
    const float* W2  = (const float*)d_in[10];
    const float* b2  = (const float*)d_in[11];
    float* out = (float*)d_out;

    cudaFuncSetAttribute(qkv_fused, cudaFuncAttributeMaxDynamicSharedMemorySize, QKVF_SMEM);
    cudaFuncSetAttribute(mlp_fused, cudaFuncAttributeMaxDynamicSharedMemorySize, MLP_SMEM);
    cudaFuncSetAttribute(attn_mma,  cudaFuncAttributeMaxDynamicSharedMemorySize, ATT_SMEM);

    // preprocessing: weight transpose+fp16, activation concat+fp16
    convert_w<<<512, 256>>>(Wq, Wk, Wv, W1, W2);
    convert_a<<<32768, 256>>>(X, STE);

    // A-resident fused QKV projections (A read once per row-block)
    qkv_fused<<<M_ / 128, 256, QKVF_SMEM>>>(bq, bk, bv);

    // flash MMA attention: block per (n, b, head-group), 12 warps
    attn_mma<<<dim3(N_, B_, 2), 384, ATT_SMEM>>>();

    // fused output MLP (fp16 single)
    mlp_fused<<<M_ / 128, 256, MLP_SMEM>>>(b1, b2, out);
}